// round 4
// baseline (speedup 1.0000x reference)
#include <cuda_runtime.h>

#define BB 128
#define SS 512
#define EE 512
#define HH 1024
#define VV 32000
#define NC 1000

typedef unsigned long long ull;

__device__ float g_pt[(size_t)VV * 2048];   // token preacts (+bias): [v][0..1023]=z, [1024..2047]=h
__device__ float g_wt2[128 * 16 * 1024];    // recurrent weights: [nb][cc][k], cc<8:z-col, cc>=8:htilde-col
__device__ float g_wfc3[125 * 1024 * 8];    // classifier weights per block
__device__ float g_h[2][BB * HH];           // double-buffered hidden state
__device__ unsigned g_bar;                  // grid barrier counter

// ---- packed f32x2 helpers ----
__device__ __forceinline__ ull pack2(float a, float b) {
    ull r; asm("mov.b64 %0, {%1, %2};" : "=l"(r) : "f"(a), "f"(b)); return r;
}
__device__ __forceinline__ void unpack2(ull v, float& a, float& b) {
    asm("mov.b64 {%0, %1}, %2;" : "=f"(a), "=f"(b) : "l"(v));
}
__device__ __forceinline__ void ffma2(ull& d, ull a, ull b) {
    asm("fma.rn.f32x2 %0, %1, %2, %0;" : "+l"(d) : "l"(a), "l"(b));
}
__device__ __forceinline__ ulonglong2 ldcgU2(const float* p) {
    ulonglong2 v;
    asm volatile("ld.global.cg.v2.b64 {%0,%1},[%2];" : "=l"(v.x), "=l"(v.y) : "l"(p));
    return v;
}
__device__ __forceinline__ float ldcgf(const float* p) {
    float v; asm volatile("ld.global.cg.f32 %0,[%1];" : "=f"(v) : "l"(p)); return v;
}
__device__ __forceinline__ void stcgf(float* p, float v) {
    asm volatile("st.global.cg.f32 [%0],%1;" :: "l"(p), "f"(v) : "memory");
}

// ---------------------------------------------------------------------------
// Prep kernels
// ---------------------------------------------------------------------------
__global__ void prep_wt(const float* __restrict__ Wz, const float* __restrict__ Wh) {
    int o = blockIdx.x * blockDim.x + threadIdx.x;
    if (o >= 128 * 16 * 1024) return;
    int k = o & 1023, cc = (o >> 10) & 15, nb = o >> 14;
    int c = cc & 7, g = cc >> 3;
    const float* W = g ? Wh : Wz;
    g_wt2[o] = W[(size_t)(512 + k) * 1024 + nb * 8 + c];
}

__global__ void prep_wfc(const float* __restrict__ Wfc) {
    int o = blockIdx.x * blockDim.x + threadIdx.x;
    if (o >= 125 * 1024 * 8) return;
    int c = o & 7, k = (o >> 3) & 1023, nb = o >> 13;
    g_wfc3[o] = Wfc[(size_t)k * NC + nb * 8 + c];
}

__global__ void zero_h0() {
    int i = blockIdx.x * blockDim.x + threadIdx.x;
    if (i < BB * HH) g_h[0][i] = 0.0f;
    if (i == 0) g_bar = 0u;
}

// ---------------------------------------------------------------------------
// ptable GEMM: P[32000 x 2048] = emb @ [Wz_top | Wh_top] + bias
// ---------------------------------------------------------------------------
__global__ __launch_bounds__(256) void ptable_gemm(
    const float* __restrict__ emb,
    const float* __restrict__ Wz, const float* __restrict__ Wh,
    const float* __restrict__ bz, const float* __restrict__ bh)
{
    __shared__ float As[8][132];
    __shared__ float Bs[8][128];
    const int tid = threadIdx.x;
    const int tx = tid & 15, ty = tid >> 4;
    const int row0 = blockIdx.y * 128;
    const int col0 = blockIdx.x * 128;
    const float* W = (col0 < 1024) ? Wz : Wh;
    const int ccol0 = col0 & 1023;

    ull acc[8][4];
#pragma unroll
    for (int i = 0; i < 8; i++)
#pragma unroll
        for (int j = 0; j < 4; j++) acc[i][j] = 0ull;

    const int arow = tid >> 1;
    const int akq = (tid & 1) * 4;
    const int bkk = tid >> 5;
    const int bj = (tid & 31) * 4;

    for (int k0 = 0; k0 < EE; k0 += 8) {
        float4 av = *(const float4*)(emb + (size_t)(row0 + arow) * EE + k0 + akq);
        float4 bv = *(const float4*)(W + (size_t)(k0 + bkk) * HH + ccol0 + bj);
        As[akq + 0][arow] = av.x;
        As[akq + 1][arow] = av.y;
        As[akq + 2][arow] = av.z;
        As[akq + 3][arow] = av.w;
        *(float4*)&Bs[bkk][bj] = bv;
        __syncthreads();
#pragma unroll
        for (int kk = 0; kk < 8; kk++) {
            float4 a0 = *(const float4*)&As[kk][ty * 8];
            float4 a1 = *(const float4*)&As[kk][ty * 8 + 4];
            ulonglong2 b0 = *(const ulonglong2*)&Bs[kk][tx * 8];
            ulonglong2 b1 = *(const ulonglong2*)&Bs[kk][tx * 8 + 4];
            float a[8] = {a0.x, a0.y, a0.z, a0.w, a1.x, a1.y, a1.z, a1.w};
#pragma unroll
            for (int i = 0; i < 8; i++) {
                ull hh = pack2(a[i], a[i]);
                ffma2(acc[i][0], hh, b0.x);
                ffma2(acc[i][1], hh, b0.y);
                ffma2(acc[i][2], hh, b1.x);
                ffma2(acc[i][3], hh, b1.y);
            }
        }
        __syncthreads();
    }

    const float* bias = (col0 < 1024) ? bz : bh;
    const int colg = ccol0 + tx * 8;
    float bvv[8];
#pragma unroll
    for (int j = 0; j < 8; j++) bvv[j] = bias[colg + j];
#pragma unroll
    for (int i = 0; i < 8; i++) {
        float v[8];
        unpack2(acc[i][0], v[0], v[1]);
        unpack2(acc[i][1], v[2], v[3]);
        unpack2(acc[i][2], v[4], v[5]);
        unpack2(acc[i][3], v[6], v[7]);
#pragma unroll
        for (int j = 0; j < 8; j++) v[j] += bvv[j];
        int row = row0 + ty * 8 + i;
        float* dst = g_pt + (size_t)row * 2048 + col0 + tx * 8;
        *(float4*)dst = make_float4(v[0], v[1], v[2], v[3]);
        *(float4*)(dst + 4) = make_float4(v[4], v[5], v[6], v[7]);
    }
}

// ---------------------------------------------------------------------------
// Persistent recurrence v2: 128 CTAs x 512 threads, all 512 steps.
// CTA nb owns h-columns c0..c0+7. Thread (r=tid>>2, q=tid&3) computes FULL-K
// dots for gate-cols {q, q+4, q+8, q+12} of row r -> owns z and htilde for
// h-cols c0+q, c0+q+4 -> thread-local gate update, NO cross-thread reduction.
// Weights in SMEM [cc][k] padded to 1028 floats/row (conflict-free broadcast).
// h read via ld.cg.v2.b64 (already packed f32x2 pairs, zero packing ALU).
// ---------------------------------------------------------------------------
#define WS_STRIDE 1028
#define RECUR_SMEM_BYTES (16 * WS_STRIDE * 4)

__global__ __launch_bounds__(512, 1) void recur_kernel(const int* __restrict__ x) {
    extern __shared__ float ws[];   // [16][1028]
    const int tid = threadIdx.x;
    const int nb = blockIdx.x;
    const int c0 = nb * 8;

    // load this block's weights once (padded rows)
    {
        const float4* src = (const float4*)(g_wt2 + (size_t)nb * 16384);
#pragma unroll
        for (int i = 0; i < 8; i++) {
            int idx = tid + i * 512;            // 0..4095 float4 slots
            int cc = idx >> 8, kq = idx & 255;
            *(float4*)(ws + cc * WS_STRIDE + kq * 4) = src[idx];
        }
    }
    __syncthreads();

    const int r = tid >> 2;
    const int q = tid & 3;
    const float* wq = ws + q * WS_STRIDE;

    for (int t = 0; t < SS; t++) {
        const float* __restrict__ hin = g_h[t & 1];
        float* __restrict__ hout = g_h[(t & 1) ^ 1];

        // ---- prefetch gate-phase inputs (consumed ~16K cycles later) ----
        int tok = x[r * SS + t];
        const float* ptp = g_pt + (size_t)tok * 2048 + c0 + q;
        float ptz0 = ptp[0];
        float ptz1 = ptp[4];
        float pth0 = ptp[1024];
        float pth1 = ptp[1028];
        float hold0 = ldcgf(hin + r * HH + c0 + q);
        float hold1 = ldcgf(hin + r * HH + c0 + q + 4);

        // ---- 4 full-K dot products ----
        const float* hrow = hin + (r << 10);
        ull acc[4];
#pragma unroll
        for (int j = 0; j < 4; j++) acc[j] = 0ull;

        ulonglong2 h01 = ldcgU2(hrow + 0);
        ulonglong2 h23 = ldcgU2(hrow + 4);
        ulonglong2 h45 = ldcgU2(hrow + 8);
        ulonglong2 h67 = ldcgU2(hrow + 12);

#pragma unroll 4
        for (int u = 0; u < 64; u++) {
            int nf = (u < 63) ? (u + 1) * 16 : 0;
            ulonglong2 n01 = ldcgU2(hrow + nf);
            ulonglong2 n23 = ldcgU2(hrow + nf + 4);
            ulonglong2 n45 = ldcgU2(hrow + nf + 8);
            ulonglong2 n67 = ldcgU2(hrow + nf + 12);
            const float* wu = wq + u * 16;
#pragma unroll
            for (int j = 0; j < 4; j++) {
                const ulonglong2* wj = (const ulonglong2*)(wu + j * (4 * WS_STRIDE));
                ulonglong2 wA = wj[0];   // k..k+3
                ulonglong2 wB = wj[1];   // k+4..k+7
                ulonglong2 wC = wj[2];   // k+8..k+11
                ulonglong2 wD = wj[3];   // k+12..k+15
                ffma2(acc[j], h01.x, wA.x);
                ffma2(acc[j], h01.y, wA.y);
                ffma2(acc[j], h23.x, wB.x);
                ffma2(acc[j], h23.y, wB.y);
                ffma2(acc[j], h45.x, wC.x);
                ffma2(acc[j], h45.y, wC.y);
                ffma2(acc[j], h67.x, wD.x);
                ffma2(acc[j], h67.y, wD.y);
            }
            h01 = n01; h23 = n23; h45 = n45; h67 = n67;
        }

        float s[4];
#pragma unroll
        for (int j = 0; j < 4; j++) {
            float a, b;
            unpack2(acc[j], a, b);
            s[j] = a + b;
        }

        // ---- thread-local gate update ----
        float z0 = 1.0f / (1.0f + __expf(-(s[0] + ptz0)));
        float z1 = 1.0f / (1.0f + __expf(-(s[1] + ptz1)));
        float t0 = tanhf(s[2] + pth0);
        float t1 = tanhf(s[3] + pth1);
        float hn0 = fmaf(z0, t0 - hold0, hold0);
        float hn1 = fmaf(z1, t1 - hold1, hold1);
        stcgf(hout + r * HH + c0 + q, hn0);
        stcgf(hout + r * HH + c0 + q + 4, hn1);

        // ---- grid barrier ----
        __threadfence();
        __syncthreads();
        if (tid == 0) {
            atomicAdd(&g_bar, 1u);
            unsigned target = (unsigned)(t + 1) * 128u;
            const volatile unsigned* vb = (const volatile unsigned*)&g_bar;
            while (*vb < target) {}
        }
        __syncthreads();
    }
}

// ---------------------------------------------------------------------------
// Final classifier: out[128 x 1000] = h_final @ Wfc + bfc
// ---------------------------------------------------------------------------
#define FINAL_SMEM_FLOATS (8192 + 2 * 4224 + 1152)
__global__ __launch_bounds__(256) void final_kernel(const float* __restrict__ bfc,
                                                    float* __restrict__ out) {
    extern __shared__ float sm[];
    float* ws = sm;
    float* hsm = sm + 8192;
    float* red = sm + 8192 + 2 * 4224;
    const int tid = threadIdx.x;
    const int nb = blockIdx.x;
    const int c0 = nb * 8;
    const float* hin = g_h[0];
    {
        const float4* src = (const float4*)(g_wfc3 + nb * 8192);
        float4* dst = (float4*)ws;
#pragma unroll
        for (int i = 0; i < 8; i++) dst[tid + i * 256] = src[tid + i * 256];
    }
    const int r = tid & 127, kh = tid >> 7;
    ull a0 = 0, a1 = 0, a2 = 0, a3 = 0;

    for (int j = 0; j < 16; j++) {
        __syncthreads();
#pragma unroll
        for (int i = 0; i < 8; i++) {
            int idx = tid + i * 256;
            int region = idx >> 10;
            int rem = idx & 1023;
            int rr = rem >> 3;
            int kq = (rem & 7) << 2;
            float4 hv = *(const float4*)(hin + rr * HH + region * 512 + j * 32 + kq);
            float* d = hsm + region * 4224 + rr * 33 + kq;
            d[0] = hv.x; d[1] = hv.y; d[2] = hv.z; d[3] = hv.w;
        }
        __syncthreads();
        const float* hrow = hsm + kh * 4224 + r * 33;
        const ulonglong2* wp = (const ulonglong2*)(ws + (kh * 512 + j * 32) * 8);
#pragma unroll
        for (int k = 0; k < 32; k++) {
            float hv = hrow[k];
            ull hh = pack2(hv, hv);
            ulonglong2 w0 = wp[k * 2];
            ulonglong2 w1 = wp[k * 2 + 1];
            ffma2(a0, hh, w0.x);
            ffma2(a1, hh, w0.y);
            ffma2(a2, hh, w1.x);
            ffma2(a3, hh, w1.y);
        }
    }
    float v[8];
    unpack2(a0, v[0], v[1]); unpack2(a1, v[2], v[3]);
    unpack2(a2, v[4], v[5]); unpack2(a3, v[6], v[7]);
    if (kh == 1) {
#pragma unroll
        for (int c = 0; c < 8; c++) red[r * 9 + c] = v[c];
    }
    __syncthreads();
    if (kh == 0) {
#pragma unroll
        for (int c = 0; c < 8; c++)
            out[r * NC + c0 + c] = v[c] + red[r * 9 + c] + bfc[c0 + c];
    }
}

// ---------------------------------------------------------------------------
extern "C" void kernel_launch(void* const* d_in, const int* in_sizes, int n_in,
                              void* d_out, int out_size) {
    const int*   x   = (const int*)  d_in[0];
    const float* emb = (const float*)d_in[1];
    const float* Wz  = (const float*)d_in[2];
    const float* bz  = (const float*)d_in[3];
    const float* Wh  = (const float*)d_in[4];
    const float* bh  = (const float*)d_in[5];
    const float* Wfc = (const float*)d_in[6];
    const float* bfc = (const float*)d_in[7];
    float* out = (float*)d_out;
    (void)in_sizes; (void)n_in; (void)out_size;

    const int final_smem = FINAL_SMEM_FLOATS * 4;
    cudaFuncSetAttribute(recur_kernel, cudaFuncAttributeMaxDynamicSharedMemorySize, RECUR_SMEM_BYTES);
    cudaFuncSetAttribute(final_kernel, cudaFuncAttributeMaxDynamicSharedMemorySize, final_smem);

    prep_wt<<<(128 * 16 * 1024) / 256, 256>>>(Wz, Wh);
    prep_wfc<<<(125 * 1024 * 8 + 255) / 256, 256>>>(Wfc);
    zero_h0<<<(BB * HH) / 256, 256>>>();
    ptable_gemm<<<dim3(16, 250), 256>>>(emb, Wz, Wh, bz, bh);

    recur_kernel<<<128, 512, RECUR_SMEM_BYTES>>>(x);

    final_kernel<<<125, 256, final_smem>>>(bfc, out);
}

// round 5
// speedup vs baseline: 2.0183x; 2.0183x over previous
#include <cuda_runtime.h>

#define BB 128
#define SS 512
#define EE 512
#define HH 1024
#define VV 32000
#define NC 1000

typedef unsigned long long ull;

__device__ float g_pt[(size_t)VV * 2048];   // token preacts (+bias): [v][0..1023]=z, [1024..2047]=h
__device__ float g_wt2[128 * 16 * 1024];    // recurrent weights: [nb][cc][k], cc<8:z-col, cc>=8:htilde-col
__device__ float g_wfc3[125 * 1024 * 8];    // classifier weights per block
__device__ float g_h[2][BB * HH];           // double-buffered hidden state
__device__ unsigned g_bar;                  // grid barrier counter

// ---- packed f32x2 helpers ----
__device__ __forceinline__ ull pack2(float a, float b) {
    ull r; asm("mov.b64 %0, {%1, %2};" : "=l"(r) : "f"(a), "f"(b)); return r;
}
__device__ __forceinline__ void unpack2(ull v, float& a, float& b) {
    asm("mov.b64 {%0, %1}, %2;" : "=f"(a), "=f"(b) : "l"(v));
}
__device__ __forceinline__ void ffma2(ull& d, ull a, ull b) {
    asm("fma.rn.f32x2 %0, %1, %2, %0;" : "+l"(d) : "l"(a), "l"(b));
}
__device__ __forceinline__ float4 ldcg4(const float* p) {
    float4 v;
    asm volatile("ld.global.cg.v4.f32 {%0,%1,%2,%3},[%4];"
                 : "=f"(v.x), "=f"(v.y), "=f"(v.z), "=f"(v.w) : "l"(p));
    return v;
}
__device__ __forceinline__ float ldcgf(const float* p) {
    float v; asm volatile("ld.global.cg.f32 %0,[%1];" : "=f"(v) : "l"(p)); return v;
}
__device__ __forceinline__ void stcgf(float* p, float v) {
    asm volatile("st.global.cg.f32 [%0],%1;" :: "l"(p), "f"(v) : "memory");
}

// ---------------------------------------------------------------------------
// Prep kernels
// ---------------------------------------------------------------------------
__global__ void prep_wt(const float* __restrict__ Wz, const float* __restrict__ Wh) {
    int o = blockIdx.x * blockDim.x + threadIdx.x;
    if (o >= 128 * 16 * 1024) return;
    int k = o & 1023, cc = (o >> 10) & 15, nb = o >> 14;
    int c = cc & 7, g = cc >> 3;
    const float* W = g ? Wh : Wz;
    g_wt2[o] = W[(size_t)(512 + k) * 1024 + nb * 8 + c];
}

__global__ void prep_wfc(const float* __restrict__ Wfc) {
    int o = blockIdx.x * blockDim.x + threadIdx.x;
    if (o >= 125 * 1024 * 8) return;
    int c = o & 7, k = (o >> 3) & 1023, nb = o >> 13;
    g_wfc3[o] = Wfc[(size_t)k * NC + nb * 8 + c];
}

__global__ void zero_h0() {
    int i = blockIdx.x * blockDim.x + threadIdx.x;
    if (i < BB * HH) g_h[0][i] = 0.0f;
    if (i == 0) g_bar = 0u;
}

// ---------------------------------------------------------------------------
// ptable GEMM: P[32000 x 2048] = emb @ [Wz_top | Wh_top] + bias
// ---------------------------------------------------------------------------
__global__ __launch_bounds__(256) void ptable_gemm(
    const float* __restrict__ emb,
    const float* __restrict__ Wz, const float* __restrict__ Wh,
    const float* __restrict__ bz, const float* __restrict__ bh)
{
    __shared__ float As[8][132];
    __shared__ float Bs[8][128];
    const int tid = threadIdx.x;
    const int tx = tid & 15, ty = tid >> 4;
    const int row0 = blockIdx.y * 128;
    const int col0 = blockIdx.x * 128;
    const float* W = (col0 < 1024) ? Wz : Wh;
    const int ccol0 = col0 & 1023;

    ull acc[8][4];
#pragma unroll
    for (int i = 0; i < 8; i++)
#pragma unroll
        for (int j = 0; j < 4; j++) acc[i][j] = 0ull;

    const int arow = tid >> 1;
    const int akq = (tid & 1) * 4;
    const int bkk = tid >> 5;
    const int bj = (tid & 31) * 4;

    for (int k0 = 0; k0 < EE; k0 += 8) {
        float4 av = *(const float4*)(emb + (size_t)(row0 + arow) * EE + k0 + akq);
        float4 bv = *(const float4*)(W + (size_t)(k0 + bkk) * HH + ccol0 + bj);
        As[akq + 0][arow] = av.x;
        As[akq + 1][arow] = av.y;
        As[akq + 2][arow] = av.z;
        As[akq + 3][arow] = av.w;
        *(float4*)&Bs[bkk][bj] = bv;
        __syncthreads();
#pragma unroll
        for (int kk = 0; kk < 8; kk++) {
            float4 a0 = *(const float4*)&As[kk][ty * 8];
            float4 a1 = *(const float4*)&As[kk][ty * 8 + 4];
            ulonglong2 b0 = *(const ulonglong2*)&Bs[kk][tx * 8];
            ulonglong2 b1 = *(const ulonglong2*)&Bs[kk][tx * 8 + 4];
            float a[8] = {a0.x, a0.y, a0.z, a0.w, a1.x, a1.y, a1.z, a1.w};
#pragma unroll
            for (int i = 0; i < 8; i++) {
                ull hh = pack2(a[i], a[i]);
                ffma2(acc[i][0], hh, b0.x);
                ffma2(acc[i][1], hh, b0.y);
                ffma2(acc[i][2], hh, b1.x);
                ffma2(acc[i][3], hh, b1.y);
            }
        }
        __syncthreads();
    }

    const float* bias = (col0 < 1024) ? bz : bh;
    const int colg = ccol0 + tx * 8;
    float bvv[8];
#pragma unroll
    for (int j = 0; j < 8; j++) bvv[j] = bias[colg + j];
#pragma unroll
    for (int i = 0; i < 8; i++) {
        float v[8];
        unpack2(acc[i][0], v[0], v[1]);
        unpack2(acc[i][1], v[2], v[3]);
        unpack2(acc[i][2], v[4], v[5]);
        unpack2(acc[i][3], v[6], v[7]);
#pragma unroll
        for (int j = 0; j < 8; j++) v[j] += bvv[j];
        int row = row0 + ty * 8 + i;
        float* dst = g_pt + (size_t)row * 2048 + col0 + tx * 8;
        *(float4*)dst = make_float4(v[0], v[1], v[2], v[3]);
        *(float4*)(dst + 4) = make_float4(v[4], v[5], v[6], v[7]);
    }
}

// ---------------------------------------------------------------------------
// Persistent recurrence v3: 128 CTAs x 512 threads.
// 16 warps = 8 k-groups (kg) x 2 row-groups (rg). Lane owns rows
// {rg*64+lane, rg*64+lane+32}, ALL 16 gate-cols, k-slice = 8 per 64-chunk.
// h staged in SMEM chunks [128][68] (conflict-free), double buffered,
// coalesced ld.cg. Weight LDS.128 warp-uniform broadcast (1:8 vs FFMA2).
// k-parity packed accumulators: zero pack instructions.
// 8-way k-group fold via SMEM partials, then thread-local gates (r=tid>>2,
// q=tid&3 owns h-cols c0+q, c0+q+4: both z and htilde).
// ---------------------------------------------------------------------------
#define WS_STRIDE 1028
#define HB_STRIDE 68
#define HBUF_FLOATS (128 * HB_STRIDE)
#define PART_STRIDE 17
#define PART_PLANE (128 * PART_STRIDE)
#define SM_HB (16 * WS_STRIDE)
#define SM_PART (SM_HB + 2 * HBUF_FLOATS)
#define RECUR_SMEM_FLOATS (SM_PART + 8 * PART_PLANE)
#define RECUR_SMEM_BYTES (RECUR_SMEM_FLOATS * 4)

__global__ __launch_bounds__(512, 1) void recur_kernel(const int* __restrict__ x) {
    extern __shared__ float sm[];
    float* ws = sm;                 // [16][1028] weights
    float* hb = sm + SM_HB;         // 2 x [128][68] h chunks
    float* part = sm + SM_PART;     // 8 x [128][17] partials

    const int tid = threadIdx.x;
    const int nb = blockIdx.x;
    const int c0 = nb * 8;

    // load this block's weights once (padded rows)
    {
        const float4* src = (const float4*)(g_wt2 + (size_t)nb * 16384);
#pragma unroll
        for (int i = 0; i < 8; i++) {
            int idx = tid + i * 512;
            int cc = idx >> 8, kq = idx & 255;
            *(float4*)(ws + cc * WS_STRIDE + kq * 4) = src[idx];
        }
    }
    __syncthreads();

    const int lane = tid & 31;
    const int warp = tid >> 5;
    const int kg = warp & 7;
    const int rg = warp >> 3;
    const int row0 = rg * 64 + lane;

    const int r = tid >> 2;          // gate row 0..127
    const int q = tid & 3;           // gate col offset

    const int lrow = tid >> 4;       // chunk-load row base 0..31
    const int lkq = (tid & 15) << 2; // chunk-load k offset 0..60

    for (int t = 0; t < SS; t++) {
        const float* __restrict__ hin = g_h[t & 1];
        float* __restrict__ hout = g_h[(t & 1) ^ 1];

        // ---- gate-phase prefetch (consumed at end of step) ----
        int tok = x[r * SS + t];
        const float* ptp = g_pt + (size_t)tok * 2048 + c0 + q;
        float ptz0 = ptp[0];
        float ptz1 = ptp[4];
        float pth0 = ptp[1024];
        float pth1 = ptp[1028];
        float hold0 = ldcgf(hin + r * HH + c0 + q);
        float hold1 = ldcgf(hin + r * HH + c0 + q + 4);

        ull acc[2][16];
#pragma unroll
        for (int i = 0; i < 2; i++)
#pragma unroll
            for (int cc = 0; cc < 16; cc++) acc[i][cc] = 0ull;

        // ---- preload chunk 0 into buffer 0 ----
        {
#pragma unroll
            for (int rd = 0; rd < 4; rd++) {
                int row = lrow + rd * 32;
                float4 v = ldcg4(hin + row * HH + lkq);
                *(float4*)(hb + row * HB_STRIDE + lkq) = v;
            }
        }

#pragma unroll 1
        for (int c = 0; c < 16; c++) {
            __syncthreads();
            // prefetch chunk c+1 into regs (consumed after compute)
            float4 pre0, pre1, pre2, pre3;
            if (c < 15) {
                const float* src = hin + (c + 1) * 64 + lkq;
                pre0 = ldcg4(src + (lrow) * HH);
                pre1 = ldcg4(src + (lrow + 32) * HH);
                pre2 = ldcg4(src + (lrow + 64) * HH);
                pre3 = ldcg4(src + (lrow + 96) * HH);
            }
            // compute chunk c from buffer c&1
            const float* hbb = hb + (c & 1) * HBUF_FLOATS;
#pragma unroll
            for (int qd = 0; qd < 2; qd++) {
                int kl = kg * 8 + qd * 4;
                ulonglong2 h0 = *(const ulonglong2*)(hbb + row0 * HB_STRIDE + kl);
                ulonglong2 h1 = *(const ulonglong2*)(hbb + (row0 + 32) * HB_STRIDE + kl);
                const float* wk = ws + c * 64 + kl;
#pragma unroll
                for (int cc = 0; cc < 16; cc++) {
                    ulonglong2 w = *(const ulonglong2*)(wk + cc * WS_STRIDE);
                    ffma2(acc[0][cc], h0.x, w.x);
                    ffma2(acc[0][cc], h0.y, w.y);
                    ffma2(acc[1][cc], h1.x, w.x);
                    ffma2(acc[1][cc], h1.y, w.y);
                }
            }
            // stage chunk c+1 into the other buffer
            if (c < 15) {
                float* dst = hb + ((c + 1) & 1) * HBUF_FLOATS + lkq;
                *(float4*)(dst + (lrow) * HB_STRIDE) = pre0;
                *(float4*)(dst + (lrow + 32) * HB_STRIDE) = pre1;
                *(float4*)(dst + (lrow + 64) * HB_STRIDE) = pre2;
                *(float4*)(dst + (lrow + 96) * HB_STRIDE) = pre3;
            }
        }

        // ---- fold k-parity, store partials [kg][row][cc] ----
        {
            float* pp = part + kg * PART_PLANE;
#pragma unroll
            for (int i = 0; i < 2; i++) {
                int rr = row0 + i * 32;
#pragma unroll
                for (int cc = 0; cc < 16; cc++) {
                    float a, b;
                    unpack2(acc[i][cc], a, b);
                    pp[rr * PART_STRIDE + cc] = a + b;
                }
            }
        }
        __syncthreads();

        // ---- 8-way fold + thread-local gates ----
        {
            float sz0 = 0, sz1 = 0, sh0 = 0, sh1 = 0;
#pragma unroll
            for (int kgi = 0; kgi < 8; kgi++) {
                const float* pr = part + kgi * PART_PLANE + r * PART_STRIDE;
                sz0 += pr[q];
                sz1 += pr[q + 4];
                sh0 += pr[q + 8];
                sh1 += pr[q + 12];
            }
            float z0 = 1.0f / (1.0f + __expf(-(sz0 + ptz0)));
            float z1 = 1.0f / (1.0f + __expf(-(sz1 + ptz1)));
            float t0 = tanhf(sh0 + pth0);
            float t1 = tanhf(sh1 + pth1);
            float hn0 = fmaf(z0, t0 - hold0, hold0);
            float hn1 = fmaf(z1, t1 - hold1, hold1);
            stcgf(hout + r * HH + c0 + q, hn0);
            stcgf(hout + r * HH + c0 + q + 4, hn1);
        }

        // ---- grid barrier ----
        __threadfence();
        __syncthreads();
        if (tid == 0) {
            atomicAdd(&g_bar, 1u);
            unsigned target = (unsigned)(t + 1) * 128u;
            const volatile unsigned* vb = (const volatile unsigned*)&g_bar;
            while (*vb < target) {}
        }
        __syncthreads();
    }
}

// ---------------------------------------------------------------------------
// Final classifier: out[128 x 1000] = h_final @ Wfc + bfc
// ---------------------------------------------------------------------------
#define FINAL_SMEM_FLOATS (8192 + 2 * 4224 + 1152)
__global__ __launch_bounds__(256) void final_kernel(const float* __restrict__ bfc,
                                                    float* __restrict__ out) {
    extern __shared__ float sm[];
    float* ws = sm;
    float* hsm = sm + 8192;
    float* red = sm + 8192 + 2 * 4224;
    const int tid = threadIdx.x;
    const int nb = blockIdx.x;
    const int c0 = nb * 8;
    const float* hin = g_h[0];
    {
        const float4* src = (const float4*)(g_wfc3 + nb * 8192);
        float4* dst = (float4*)ws;
#pragma unroll
        for (int i = 0; i < 8; i++) dst[tid + i * 256] = src[tid + i * 256];
    }
    const int r = tid & 127, kh = tid >> 7;
    ull a0 = 0, a1 = 0, a2 = 0, a3 = 0;

    for (int j = 0; j < 16; j++) {
        __syncthreads();
#pragma unroll
        for (int i = 0; i < 8; i++) {
            int idx = tid + i * 256;
            int region = idx >> 10;
            int rem = idx & 1023;
            int rr = rem >> 3;
            int kq = (rem & 7) << 2;
            float4 hv = *(const float4*)(hin + rr * HH + region * 512 + j * 32 + kq);
            float* d = hsm + region * 4224 + rr * 33 + kq;
            d[0] = hv.x; d[1] = hv.y; d[2] = hv.z; d[3] = hv.w;
        }
        __syncthreads();
        const float* hrow = hsm + kh * 4224 + r * 33;
        const ulonglong2* wp = (const ulonglong2*)(ws + (kh * 512 + j * 32) * 8);
#pragma unroll
        for (int k = 0; k < 32; k++) {
            float hv = hrow[k];
            ull hh = pack2(hv, hv);
            ulonglong2 w0 = wp[k * 2];
            ulonglong2 w1 = wp[k * 2 + 1];
            ffma2(a0, hh, w0.x);
            ffma2(a1, hh, w0.y);
            ffma2(a2, hh, w1.x);
            ffma2(a3, hh, w1.y);
        }
    }
    float v[8];
    unpack2(a0, v[0], v[1]); unpack2(a1, v[2], v[3]);
    unpack2(a2, v[4], v[5]); unpack2(a3, v[6], v[7]);
    if (kh == 1) {
#pragma unroll
        for (int c = 0; c < 8; c++) red[r * 9 + c] = v[c];
    }
    __syncthreads();
    if (kh == 0) {
#pragma unroll
        for (int c = 0; c < 8; c++)
            out[r * NC + c0 + c] = v[c] + red[r * 9 + c] + bfc[c0 + c];
    }
}

// ---------------------------------------------------------------------------
extern "C" void kernel_launch(void* const* d_in, const int* in_sizes, int n_in,
                              void* d_out, int out_size) {
    const int*   x   = (const int*)  d_in[0];
    const float* emb = (const float*)d_in[1];
    const float* Wz  = (const float*)d_in[2];
    const float* bz  = (const float*)d_in[3];
    const float* Wh  = (const float*)d_in[4];
    const float* bh  = (const float*)d_in[5];
    const float* Wfc = (const float*)d_in[6];
    const float* bfc = (const float*)d_in[7];
    float* out = (float*)d_out;
    (void)in_sizes; (void)n_in; (void)out_size;

    const int final_smem = FINAL_SMEM_FLOATS * 4;
    cudaFuncSetAttribute(recur_kernel, cudaFuncAttributeMaxDynamicSharedMemorySize, RECUR_SMEM_BYTES);
    cudaFuncSetAttribute(final_kernel, cudaFuncAttributeMaxDynamicSharedMemorySize, final_smem);

    prep_wt<<<(128 * 16 * 1024) / 256, 256>>>(Wz, Wh);
    prep_wfc<<<(125 * 1024 * 8 + 255) / 256, 256>>>(Wfc);
    zero_h0<<<(BB * HH) / 256, 256>>>();
    ptable_gemm<<<dim3(16, 250), 256>>>(emb, Wz, Wh, bz, bh);

    recur_kernel<<<128, 512, RECUR_SMEM_BYTES>>>(x);

    final_kernel<<<125, 256, final_smem>>>(bfc, out);
}

// round 7
// speedup vs baseline: 2.7891x; 1.3819x over previous
#include <cuda_runtime.h>
#include <cuda_bf16.h>
#include <cstdint>

#define BB 128
#define SS 512
#define EE 512
#define HH 1024
#define VV 32000
#define NC 1000

typedef unsigned long long ull;

// ---------------- global scratch ----------------
__device__ float g_pt[(size_t)VV * 2048];        // token preacts (+bias): [v][0..1023]=z, [1024..2047]=htilde
__device__ unsigned char g_bfrag[64 * 131072];   // per-CTA B fragments (bf16, mma frag order)
__device__ unsigned char g_afrag[2 * 64 * 8 * 512]; // h as bf16 hi/lo A fragments: [pass][kt][mt][512B]
__device__ float g_wfc3[125 * 1024 * 8];         // classifier weights per block
__device__ float g_hf[BB * HH];                  // final hidden state fp32
__device__ unsigned g_bar;                       // grid barrier counter

// ---------------- helpers ----------------
__device__ __forceinline__ ull pack2(float a, float b) {
    ull r; asm("mov.b64 %0, {%1, %2};" : "=l"(r) : "f"(a), "f"(b)); return r;
}
__device__ __forceinline__ void unpack2(ull v, float& a, float& b) {
    asm("mov.b64 {%0, %1}, %2;" : "=f"(a), "=f"(b) : "l"(v));
}
__device__ __forceinline__ void ffma2(ull& d, ull a, ull b) {
    asm("fma.rn.f32x2 %0, %1, %2, %0;" : "+l"(d) : "l"(a), "l"(b));
}
__device__ __forceinline__ float4 ldcg4(const void* p) {
    float4 v;
    asm volatile("ld.global.cg.v4.f32 {%0,%1,%2,%3},[%4];"
                 : "=f"(v.x), "=f"(v.y), "=f"(v.z), "=f"(v.w) : "l"(p));
    return v;
}
__device__ __forceinline__ uint4 ldcgu4(const void* p) {
    uint4 v;
    asm volatile("ld.global.cg.v4.b32 {%0,%1,%2,%3},[%4];"
                 : "=r"(v.x), "=r"(v.y), "=r"(v.z), "=r"(v.w) : "l"(p));
    return v;
}
__device__ __forceinline__ void stcgu4(void* p, uint4 v) {
    asm volatile("st.global.cg.v4.b32 [%0],{%1,%2,%3,%4};"
                 :: "l"(p), "r"(v.x), "r"(v.y), "r"(v.z), "r"(v.w) : "memory");
}
// packed bf16 pair: low half = v0, high half = v1
__device__ __forceinline__ uint32_t bfpair(float v0, float v1) {
    uint32_t r; asm("cvt.rn.bf16x2.f32 %0, %1, %2;" : "=r"(r) : "f"(v1), "f"(v0)); return r;
}
// legacy tensor-core mma (compute_103-safe, no 'a' features)
__device__ __forceinline__ void hmma(float* d, const uint4& a, const uint2& b) {
    asm("mma.sync.aligned.m16n8k16.row.col.f32.bf16.bf16.f32 "
        "{%0,%1,%2,%3},{%4,%5,%6,%7},{%8,%9},{%0,%1,%2,%3};"
        : "+f"(d[0]), "+f"(d[1]), "+f"(d[2]), "+f"(d[3])
        : "r"(a.x), "r"(a.y), "r"(a.z), "r"(a.w), "r"(b.x), "r"(b.y));
}

// ---------------------------------------------------------------------------
// Prep: W -> B fragments. CTA nb owns h-cols nb*16..+15. B cols j(0..63):
// j>>4 = kind {0:Wz_hi, 1:Wh_hi, 2:Wz_lo, 3:Wh_lo}, c_local = j&15.
// Fragment (kt, nt, lane, breg): k = kt*16+(l&3)*2+breg*8, col = nt*8+(l>>2).
// ---------------------------------------------------------------------------
__global__ void prep_bfrag(const float* __restrict__ Wz, const float* __restrict__ Wh) {
    int o = blockIdx.x * blockDim.x + threadIdx.x;   // 64*64*8*32*2 = 2097152
    int b = o & 1, l = (o >> 1) & 31, nt = (o >> 6) & 7, kt = (o >> 9) & 63, nb = o >> 15;
    int k = kt * 16 + (l & 3) * 2 + b * 8;
    int j = nt * 8 + (l >> 2);
    int hcol = nb * 16 + (j & 15);
    int kind = j >> 4;
    const float* W = (kind & 1) ? Wh : Wz;
    float w0 = W[(size_t)(512 + k) * 1024 + hcol];
    float w1 = W[(size_t)(512 + k + 1) * 1024 + hcol];
    uint32_t hi = bfpair(w0, w1);
    uint32_t val;
    if (kind < 2) val = hi;
    else {
        float r0 = w0 - __uint_as_float(hi << 16);
        float r1 = w1 - __uint_as_float(hi & 0xFFFF0000u);
        val = bfpair(r0, r1);
    }
    ((uint32_t*)g_bfrag)[(size_t)nb * 32768 + (size_t)((kt * 8 + nt) * 32 + l) * 2 + b] = val;
}

__global__ void prep_wfc(const float* __restrict__ Wfc) {
    int o = blockIdx.x * blockDim.x + threadIdx.x;
    if (o >= 125 * 1024 * 8) return;
    int c = o & 7, k = (o >> 3) & 1023, nb = o >> 13;
    g_wfc3[o] = Wfc[(size_t)k * NC + nb * 8 + c];
}

__global__ void zero_afrag() {
    int i = blockIdx.x * blockDim.x + threadIdx.x;   // 32768 uint4
    ((uint4*)g_afrag)[i] = make_uint4(0, 0, 0, 0);
    if (i == 0) g_bar = 0u;
}

// ---------------------------------------------------------------------------
// ptable GEMM: P[32000 x 2048] = emb @ [Wz_top | Wh_top] + bias  (fp32 FFMA2)
// ---------------------------------------------------------------------------
__global__ __launch_bounds__(256) void ptable_gemm(
    const float* __restrict__ emb,
    const float* __restrict__ Wz, const float* __restrict__ Wh,
    const float* __restrict__ bz, const float* __restrict__ bh)
{
    __shared__ float As[8][132];
    __shared__ float Bs[8][128];
    const int tid = threadIdx.x;
    const int tx = tid & 15, ty = tid >> 4;
    const int row0 = blockIdx.y * 128;
    const int col0 = blockIdx.x * 128;
    const float* W = (col0 < 1024) ? Wz : Wh;
    const int ccol0 = col0 & 1023;

    ull acc[8][4];
#pragma unroll
    for (int i = 0; i < 8; i++)
#pragma unroll
        for (int j = 0; j < 4; j++) acc[i][j] = 0ull;

    const int arow = tid >> 1;
    const int akq = (tid & 1) * 4;
    const int bkk = tid >> 5;
    const int bj = (tid & 31) * 4;

    for (int k0 = 0; k0 < EE; k0 += 8) {
        float4 av = *(const float4*)(emb + (size_t)(row0 + arow) * EE + k0 + akq);
        float4 bv = *(const float4*)(W + (size_t)(k0 + bkk) * HH + ccol0 + bj);
        As[akq + 0][arow] = av.x;
        As[akq + 1][arow] = av.y;
        As[akq + 2][arow] = av.z;
        As[akq + 3][arow] = av.w;
        *(float4*)&Bs[bkk][bj] = bv;
        __syncthreads();
#pragma unroll
        for (int kk = 0; kk < 8; kk++) {
            float4 a0 = *(const float4*)&As[kk][ty * 8];
            float4 a1 = *(const float4*)&As[kk][ty * 8 + 4];
            ulonglong2 b0 = *(const ulonglong2*)&Bs[kk][tx * 8];
            ulonglong2 b1 = *(const ulonglong2*)&Bs[kk][tx * 8 + 4];
            float a[8] = {a0.x, a0.y, a0.z, a0.w, a1.x, a1.y, a1.z, a1.w};
#pragma unroll
            for (int i = 0; i < 8; i++) {
                ull hh = pack2(a[i], a[i]);
                ffma2(acc[i][0], hh, b0.x);
                ffma2(acc[i][1], hh, b0.y);
                ffma2(acc[i][2], hh, b1.x);
                ffma2(acc[i][3], hh, b1.y);
            }
        }
        __syncthreads();
    }

    const float* bias = (col0 < 1024) ? bz : bh;
    const int colg = ccol0 + tx * 8;
    float bvv[8];
#pragma unroll
    for (int j = 0; j < 8; j++) bvv[j] = bias[colg + j];
#pragma unroll
    for (int i = 0; i < 8; i++) {
        float v[8];
        unpack2(acc[i][0], v[0], v[1]);
        unpack2(acc[i][1], v[2], v[3]);
        unpack2(acc[i][2], v[4], v[5]);
        unpack2(acc[i][3], v[6], v[7]);
#pragma unroll
        for (int j = 0; j < 8; j++) v[j] += bvv[j];
        int row = row0 + ty * 8 + i;
        float* dst = g_pt + (size_t)row * 2048 + col0 + tx * 8;
        *(float4*)dst = make_float4(v[0], v[1], v[2], v[3]);
        *(float4*)(dst + 4) = make_float4(v[4], v[5], v[6], v[7]);
    }
}

// ---------------------------------------------------------------------------
// Persistent HMMA recurrence: 64 CTAs x 256 threads (8 warps).
// warp w: kq = w>>1 (K quarter, 16 k-tiles), mh = w&1 (4 m-tiles).
// D[128x64] = sum_p A_p[128x1024] @ B[1024x64], p in {hi,lo}.
// Gate fold per lane: z = D[c]+D[c+32], ht = D[c+16]+D[c+48]  (thread-local).
// SMEM: B frags 128KB + reduction 64KB + pt stage 18KB.
// ---------------------------------------------------------------------------
#define RED_OFF 131072
#define PTS_OFF 196608
#define RECUR_SMEM_BYTES 215040

__global__ __launch_bounds__(256, 1) void recur_kernel(const int* __restrict__ x) {
    extern __shared__ char smem[];
    uint32_t* bs = (uint32_t*)smem;
    float* red = (float*)(smem + RED_OFF);
    float* pts = (float*)(smem + PTS_OFF);

    const int tid = threadIdx.x, lane = tid & 31, w = tid >> 5;
    const int nb = blockIdx.x;
    const int kq = w >> 1, mh = w & 1;
    const int gr = lane >> 2, gc = lane & 3;

    // load resident B fragments (128KB linear)
    {
        const uint4* src = (const uint4*)(g_bfrag + (size_t)nb * 131072);
        uint4* dst = (uint4*)smem;
#pragma unroll
        for (int i = 0; i < 32; i++) dst[tid + i * 256] = ldcgu4(src + tid + i * 256);
    }
    __syncthreads();

    float hold[4][8];
#pragma unroll
    for (int m = 0; m < 4; m++)
#pragma unroll
        for (int j = 0; j < 8; j++) hold[m][j] = 0.0f;

    for (int t = 0; t < SS; t++) {
        // ---- pt staging by warps 4-7 (one thread per batch row) ----
        if (w >= 4) {
            int r = (w - 4) * 32 + lane;
            int tok = __ldg(x + r * SS + t);
            const float* p = g_pt + (size_t)tok * 2048 + nb * 16;
#pragma unroll
            for (int i = 0; i < 4; i++)
                *(float4*)(pts + r * 36 + i * 4) = ldcg4(p + i * 4);
#pragma unroll
            for (int i = 0; i < 4; i++)
                *(float4*)(pts + r * 36 + 16 + i * 4) = ldcg4(p + 1024 + i * 4);
        }

        // ---- MMA phase ----
        float acc[4][8][4];
#pragma unroll
        for (int m = 0; m < 4; m++)
#pragma unroll
            for (int nt = 0; nt < 8; nt++)
#pragma unroll
                for (int j = 0; j < 4; j++) acc[m][nt][j] = 0.0f;

#pragma unroll 1
        for (int p2 = 0; p2 < 2; p2++) {
#pragma unroll 2
            for (int i = 0; i < 16; i++) {
                int kt = kq * 16 + i;
                uint4 a[4];
#pragma unroll
                for (int m = 0; m < 4; m++)
                    a[m] = ldcgu4(g_afrag + (size_t)(((p2 * 64 + kt) * 8) + mh * 4 + m) * 512 + lane * 16);
                uint2 b[8];
#pragma unroll
                for (int nt = 0; nt < 8; nt++)
                    b[nt] = *(const uint2*)(bs + ((kt * 8 + nt) * 32 + lane) * 2);
#pragma unroll
                for (int m = 0; m < 4; m++)
#pragma unroll
                    for (int nt = 0; nt < 8; nt++)
                        hmma(acc[m][nt], a[m], b[nt]);
            }
        }

        // ---- K reduction: round 1 (kq2,3 -> kq0,1), round 2 (kq1 -> kq0) ----
        __syncthreads();
        if (kq >= 2) {
            float* dst = red + ((kq - 2) * 2 + mh) * 4096;
#pragma unroll
            for (int m = 0; m < 4; m++)
#pragma unroll
                for (int nt = 0; nt < 8; nt++)
                    *(float4*)(dst + (m * 8 + nt) * 128 + lane * 4) = *(float4*)acc[m][nt];
        }
        __syncthreads();
        if (kq < 2) {
            const float* src = red + (kq * 2 + mh) * 4096;
#pragma unroll
            for (int m = 0; m < 4; m++)
#pragma unroll
                for (int nt = 0; nt < 8; nt++) {
                    float4 v = *(const float4*)(src + (m * 8 + nt) * 128 + lane * 4);
                    acc[m][nt][0] += v.x; acc[m][nt][1] += v.y;
                    acc[m][nt][2] += v.z; acc[m][nt][3] += v.w;
                }
        }
        __syncthreads();
        if (kq == 1) {
            float* dst = red + mh * 4096;
#pragma unroll
            for (int m = 0; m < 4; m++)
#pragma unroll
                for (int nt = 0; nt < 8; nt++)
                    *(float4*)(dst + (m * 8 + nt) * 128 + lane * 4) = *(float4*)acc[m][nt];
        }
        __syncthreads();

        // ---- gates + A-fragment writeback (kq0 warps only) ----
        if (kq == 0) {
            const float* src = red + mh * 4096;
#pragma unroll
            for (int m = 0; m < 4; m++) {
                // finish reduction for this m-tile
#pragma unroll
                for (int nt = 0; nt < 8; nt++) {
                    float4 v = *(const float4*)(src + (m * 8 + nt) * 128 + lane * 4);
                    acc[m][nt][0] += v.x; acc[m][nt][1] += v.y;
                    acc[m][nt][2] += v.z; acc[m][nt][3] += v.w;
                }
                int mtg = mh * 4 + m;
                int r0 = mtg * 16 + gr, r1 = r0 + 8;
                const float* pr0 = pts + r0 * 36;
                const float* pr1 = pts + r1 * 36;
                float hn[8];
#pragma unroll
                for (int grp = 0; grp < 2; grp++) {     // k-col group: 2gc / 2gc+8
                    int n0 = grp, kc = 2 * gc + grp * 8;
                    float2 pz0 = *(const float2*)(pr0 + kc);
                    float2 ph0 = *(const float2*)(pr0 + 16 + kc);
                    float2 pz1 = *(const float2*)(pr1 + kc);
                    float2 ph1 = *(const float2*)(pr1 + 16 + kc);
                    float zp[4], hp[4];
#pragma unroll
                    for (int j = 0; j < 4; j++) {
                        zp[j] = acc[m][n0][j] + acc[m][n0 + 4][j];
                        hp[j] = acc[m][n0 + 2][j] + acc[m][n0 + 6][j];
                    }
                    float pzv[4] = {pz0.x, pz0.y, pz1.x, pz1.y};
                    float phv[4] = {ph0.x, ph0.y, ph1.x, ph1.y};
#pragma unroll
                    for (int j = 0; j < 4; j++) {
                        float z = 1.0f / (1.0f + __expf(-(zp[j] + pzv[j])));
                        float th = tanhf(hp[j] + phv[j]);
                        float ho = hold[m][grp * 4 + j];
                        float v = fmaf(z, th - ho, ho);
                        hn[grp * 4 + j] = v;
                        hold[m][grp * 4 + j] = v;
                    }
                }
                // pack A fragments: a0=(r0,kc0/1) a1=(r1,kc0/1) a2=(r0,kc8/9) a3=(r1,kc8/9)
                uint4 hi, lo;
                hi.x = bfpair(hn[0], hn[1]);
                hi.y = bfpair(hn[2], hn[3]);
                hi.z = bfpair(hn[4], hn[5]);
                hi.w = bfpair(hn[6], hn[7]);
                float r00 = hn[0] - __uint_as_float(hi.x << 16);
                float r01 = hn[1] - __uint_as_float(hi.x & 0xFFFF0000u);
                float r10 = hn[2] - __uint_as_float(hi.y << 16);
                float r11 = hn[3] - __uint_as_float(hi.y & 0xFFFF0000u);
                float r20 = hn[4] - __uint_as_float(hi.z << 16);
                float r21 = hn[5] - __uint_as_float(hi.z & 0xFFFF0000u);
                float r30 = hn[6] - __uint_as_float(hi.w << 16);
                float r31 = hn[7] - __uint_as_float(hi.w & 0xFFFF0000u);
                lo.x = bfpair(r00, r01);
                lo.y = bfpair(r10, r11);
                lo.z = bfpair(r20, r21);
                lo.w = bfpair(r30, r31);
                stcgu4(g_afrag + (size_t)((nb * 8) + mtg) * 512 + lane * 16, hi);
                stcgu4(g_afrag + (size_t)(((64 + nb) * 8) + mtg) * 512 + lane * 16, lo);
                if (t == SS - 1) {
                    int cb = nb * 16 + 2 * gc;
                    g_hf[r0 * HH + cb] = hn[0];
                    g_hf[r0 * HH + cb + 1] = hn[1];
                    g_hf[r1 * HH + cb] = hn[2];
                    g_hf[r1 * HH + cb + 1] = hn[3];
                    g_hf[r0 * HH + cb + 8] = hn[4];
                    g_hf[r0 * HH + cb + 9] = hn[5];
                    g_hf[r1 * HH + cb + 8] = hn[6];
                    g_hf[r1 * HH + cb + 9] = hn[7];
                }
            }
        }

        // ---- grid barrier ----
        __threadfence();
        __syncthreads();
        if (tid == 0) {
            atomicAdd(&g_bar, 1u);
            unsigned target = (unsigned)(t + 1) * 64u;
            const volatile unsigned* vb = (const volatile unsigned*)&g_bar;
            while (*vb < target) {}
        }
        __syncthreads();
    }
}

// ---------------------------------------------------------------------------
// Final classifier: out[128 x 1000] = h_final @ Wfc + bfc
// ---------------------------------------------------------------------------
#define FINAL_SMEM_FLOATS (8192 + 2 * 4224 + 1152)
__global__ __launch_bounds__(256) void final_kernel(const float* __restrict__ bfc,
                                                    float* __restrict__ out) {
    extern __shared__ float sm[];
    float* ws = sm;
    float* hsm = sm + 8192;
    float* red = sm + 8192 + 2 * 4224;
    const int tid = threadIdx.x;
    const int nb = blockIdx.x;
    const int c0 = nb * 8;
    const float* hin = g_hf;
    {
        const float4* src = (const float4*)(g_wfc3 + nb * 8192);
        float4* dst = (float4*)ws;
#pragma unroll
        for (int i = 0; i < 8; i++) dst[tid + i * 256] = src[tid + i * 256];
    }
    const int r = tid & 127, kh = tid >> 7;
    ull a0 = 0, a1 = 0, a2 = 0, a3 = 0;

    for (int j = 0; j < 16; j++) {
        __syncthreads();
#pragma unroll
        for (int i = 0; i < 8; i++) {
            int idx = tid + i * 256;
            int region = idx >> 10;
            int rem = idx & 1023;
            int rr = rem >> 3;
            int kq = (rem & 7) << 2;
            float4 hv = *(const float4*)(hin + rr * HH + region * 512 + j * 32 + kq);
            float* d = hsm + region * 4224 + rr * 33 + kq;
            d[0] = hv.x; d[1] = hv.y; d[2] = hv.z; d[3] = hv.w;
        }
        __syncthreads();
        const float* hrow = hsm + kh * 4224 + r * 33;
        const ulonglong2* wp = (const ulonglong2*)(ws + (kh * 512 + j * 32) * 8);
#pragma unroll
        for (int k = 0; k < 32; k++) {
            float hv = hrow[k];
            ull hh = pack2(hv, hv);
            ulonglong2 w0 = wp[k * 2];
            ulonglong2 w1 = wp[k * 2 + 1];
            ffma2(a0, hh, w0.x);
            ffma2(a1, hh, w0.y);
            ffma2(a2, hh, w1.x);
            ffma2(a3, hh, w1.y);
        }
    }
    float v[8];
    unpack2(a0, v[0], v[1]); unpack2(a1, v[2], v[3]);
    unpack2(a2, v[4], v[5]); unpack2(a3, v[6], v[7]);
    if (kh == 1) {
#pragma unroll
        for (int c = 0; c < 8; c++) red[r * 9 + c] = v[c];
    }
    __syncthreads();
    if (kh == 0) {
#pragma unroll
        for (int c = 0; c < 8; c++)
            out[r * NC + c0 + c] = v[c] + red[r * 9 + c] + bfc[c0 + c];
    }
}

// ---------------------------------------------------------------------------
extern "C" void kernel_launch(void* const* d_in, const int* in_sizes, int n_in,
                              void* d_out, int out_size) {
    const int*   x   = (const int*)  d_in[0];
    const float* emb = (const float*)d_in[1];
    const float* Wz  = (const float*)d_in[2];
    const float* bz  = (const float*)d_in[3];
    const float* Wh  = (const float*)d_in[4];
    const float* bh  = (const float*)d_in[5];
    const float* Wfc = (const float*)d_in[6];
    const float* bfc = (const float*)d_in[7];
    float* out = (float*)d_out;
    (void)in_sizes; (void)n_in; (void)out_size;

    const int final_smem = FINAL_SMEM_FLOATS * 4;
    cudaFuncSetAttribute(recur_kernel, cudaFuncAttributeMaxDynamicSharedMemorySize, RECUR_SMEM_BYTES);
    cudaFuncSetAttribute(final_kernel, cudaFuncAttributeMaxDynamicSharedMemorySize, final_smem);

    prep_bfrag<<<8192, 256>>>(Wz, Wh);
    prep_wfc<<<(125 * 1024 * 8 + 255) / 256, 256>>>(Wfc);
    zero_afrag<<<128, 256>>>();
    ptable_gemm<<<dim3(16, 250), 256>>>(emb, Wz, Wh, bz, bh);

    recur_kernel<<<64, 256, RECUR_SMEM_BYTES>>>(x);

    final_kernel<<<125, 256, final_smem>>>(bfc, out);
}

// round 8
// speedup vs baseline: 3.8858x; 1.3932x over previous
#include <cuda_runtime.h>
#include <cuda_bf16.h>
#include <cstdint>

#define BB 128
#define SS 512
#define EE 512
#define HH 1024
#define VV 32000
#define NC 1000

typedef unsigned long long ull;

// ---------------- global scratch ----------------
__device__ float g_pt[(size_t)VV * 2048];          // token preacts (+bias): [v][0..1023]=z, [1024..2047]=htilde
__device__ unsigned char g_bfrag[64 * 131072];     // per-CTA recurrent B fragments (bf16)
__device__ unsigned char g_afrag[2 * 64 * 8 * 512];// h bf16 hi/lo A fragments: [pass][kt][mt][512B]
__device__ unsigned char g_efh[(size_t)2000 * 32 * 512];  // emb hi A-fragments
__device__ unsigned char g_efl[(size_t)2000 * 32 * 512];  // emb lo A-fragments
__device__ unsigned char g_wtfh[32 * 65536];       // Wtop hi B-fragments per col-tile
__device__ unsigned char g_wtfl[32 * 65536];       // Wtop lo B-fragments per col-tile
__device__ float g_wfc3[125 * 1024 * 8];           // classifier weights per block
__device__ float g_hf[BB * HH];                    // final hidden state fp32
__device__ unsigned g_bar;                         // grid barrier counter

// ---------------- helpers ----------------
__device__ __forceinline__ ull pack2(float a, float b) {
    ull r; asm("mov.b64 %0, {%1, %2};" : "=l"(r) : "f"(a), "f"(b)); return r;
}
__device__ __forceinline__ void unpack2(ull v, float& a, float& b) {
    asm("mov.b64 {%0, %1}, %2;" : "=f"(a), "=f"(b) : "l"(v));
}
__device__ __forceinline__ void ffma2(ull& d, ull a, ull b) {
    asm("fma.rn.f32x2 %0, %1, %2, %0;" : "+l"(d) : "l"(a), "l"(b));
}
__device__ __forceinline__ float4 ldcg4(const void* p) {
    float4 v;
    asm volatile("ld.global.cg.v4.f32 {%0,%1,%2,%3},[%4];"
                 : "=f"(v.x), "=f"(v.y), "=f"(v.z), "=f"(v.w) : "l"(p));
    return v;
}
__device__ __forceinline__ uint4 ldcgu4(const void* p) {
    uint4 v;
    asm volatile("ld.global.cg.v4.b32 {%0,%1,%2,%3},[%4];"
                 : "=r"(v.x), "=r"(v.y), "=r"(v.z), "=r"(v.w) : "l"(p));
    return v;
}
__device__ __forceinline__ void stcgu4(void* p, uint4 v) {
    asm volatile("st.global.cg.v4.b32 [%0],{%1,%2,%3,%4};"
                 :: "l"(p), "r"(v.x), "r"(v.y), "r"(v.z), "r"(v.w) : "memory");
}
// packed bf16 pair: low half = v0, high half = v1
__device__ __forceinline__ uint32_t bfpair(float v0, float v1) {
    uint32_t r; asm("cvt.rn.bf16x2.f32 %0, %1, %2;" : "=r"(r) : "f"(v1), "f"(v0)); return r;
}
__device__ __forceinline__ void hmma(float* d, const uint4& a, const uint2& b) {
    asm("mma.sync.aligned.m16n8k16.row.col.f32.bf16.bf16.f32 "
        "{%0,%1,%2,%3},{%4,%5,%6,%7},{%8,%9},{%0,%1,%2,%3};"
        : "+f"(d[0]), "+f"(d[1]), "+f"(d[2]), "+f"(d[3])
        : "r"(a.x), "r"(a.y), "r"(a.z), "r"(a.w), "r"(b.x), "r"(b.y));
}

// ---------------------------------------------------------------------------
// Prep: recurrent W -> B fragments (uint4-paired layout).
// idx = nb*32768 + ((kt*4 + nt/2)*32 + l)*4 + (nt&1)*2 + breg
// ---------------------------------------------------------------------------
__global__ void prep_bfrag(const float* __restrict__ Wz, const float* __restrict__ Wh) {
    int o = blockIdx.x * blockDim.x + threadIdx.x;   // 2097152
    int b = o & 1, l = (o >> 1) & 31, nt = (o >> 6) & 7, kt = (o >> 9) & 63, nb = o >> 15;
    int k = kt * 16 + (l & 3) * 2 + b * 8;
    int j = nt * 8 + (l >> 2);
    int hcol = nb * 16 + (j & 15);
    int kind = j >> 4;
    const float* W = (kind & 1) ? Wh : Wz;
    float w0 = W[(size_t)(512 + k) * 1024 + hcol];
    float w1 = W[(size_t)(512 + k + 1) * 1024 + hcol];
    uint32_t hi = bfpair(w0, w1);
    uint32_t val;
    if (kind < 2) val = hi;
    else {
        float r0 = w0 - __uint_as_float(hi << 16);
        float r1 = w1 - __uint_as_float(hi & 0xFFFF0000u);
        val = bfpair(r0, r1);
    }
    ((uint32_t*)g_bfrag)[(size_t)nb * 32768 + (size_t)((kt * 4 + (nt >> 1)) * 32 + l) * 4 + (nt & 1) * 2 + b] = val;
}

// emb -> hi/lo A fragments: [mt 2000][kt 32][512B]
__global__ void prep_efrag(const float* __restrict__ emb) {
    int o = blockIdx.x * blockDim.x + threadIdx.x;   // 8192000
    int j = o & 3, l = (o >> 2) & 31, kt = (o >> 7) & 31, mt = o >> 12;
    int r = mt * 16 + (j & 1) * 8 + (l >> 2);
    int k = kt * 16 + (j >> 1) * 8 + (l & 3) * 2;
    float e0 = emb[(size_t)r * EE + k];
    float e1 = emb[(size_t)r * EE + k + 1];
    uint32_t hi = bfpair(e0, e1);
    float r0 = e0 - __uint_as_float(hi << 16);
    float r1 = e1 - __uint_as_float(hi & 0xFFFF0000u);
    size_t idx = ((size_t)(mt * 32 + kt) * 32 + l) * 4 + j;
    ((uint32_t*)g_efh)[idx] = hi;
    ((uint32_t*)g_efl)[idx] = bfpair(r0, r1);
}

// Wtop -> hi/lo B fragments per col-tile: idx = o (layout matches decode)
__global__ void prep_wtf(const float* __restrict__ Wz, const float* __restrict__ Wh) {
    int o = blockIdx.x * blockDim.x + threadIdx.x;   // 524288
    int j = o & 3, l = (o >> 2) & 31, ntp = (o >> 7) & 3, kt = (o >> 9) & 31, ct = o >> 14;
    int nt = ntp * 2 + (j >> 1);
    int breg = j & 1;
    int colg = ct * 64 + nt * 8 + (l >> 2);
    int k = kt * 16 + (l & 3) * 2 + breg * 8;
    const float* W = (colg < 1024) ? Wz : Wh;
    int c = colg & 1023;
    float w0 = W[(size_t)k * 1024 + c];
    float w1 = W[(size_t)(k + 1) * 1024 + c];
    uint32_t hi = bfpair(w0, w1);
    float r0 = w0 - __uint_as_float(hi << 16);
    float r1 = w1 - __uint_as_float(hi & 0xFFFF0000u);
    ((uint32_t*)g_wtfh)[o] = hi;
    ((uint32_t*)g_wtfl)[o] = bfpair(r0, r1);
}

__global__ void prep_wfc(const float* __restrict__ Wfc) {
    int o = blockIdx.x * blockDim.x + threadIdx.x;
    if (o >= 125 * 1024 * 8) return;
    int c = o & 7, k = (o >> 3) & 1023, nb = o >> 13;
    g_wfc3[o] = Wfc[(size_t)k * NC + nb * 8 + c];
}

__global__ void zero_afrag() {
    int i = blockIdx.x * blockDim.x + threadIdx.x;   // 32768 uint4
    ((uint4*)g_afrag)[i] = make_uint4(0, 0, 0, 0);
    if (i == 0) g_bar = 0u;
}

// ---------------------------------------------------------------------------
// ptable via HMMA: P[32000 x 2048] = emb @ Wtop + bias, exact bf16 hi/lo
// (3 products). Grid (32 ct, 250 rt) x 256 thr. W tile resident in SMEM.
// ---------------------------------------------------------------------------
__global__ __launch_bounds__(256) void ptable_hmma(const float* __restrict__ bz,
                                                   const float* __restrict__ bh) {
    extern __shared__ char smem[];
    uint4* smh = (uint4*)smem;            // 64KB hi
    uint4* sml = (uint4*)(smem + 65536);  // 64KB lo
    const int tid = threadIdx.x, lane = tid & 31, w = tid >> 5;
    const int ct = blockIdx.x, rt = blockIdx.y;
    const int mt = rt * 8 + w;

    {
        const uint4* sh = (const uint4*)(g_wtfh + (size_t)ct * 65536);
        const uint4* sl = (const uint4*)(g_wtfl + (size_t)ct * 65536);
#pragma unroll
        for (int i = 0; i < 16; i++) {
            smh[tid + i * 256] = ldcgu4(sh + tid + i * 256);
            sml[tid + i * 256] = ldcgu4(sl + tid + i * 256);
        }
    }
    __syncthreads();

    float acc[8][4];
#pragma unroll
    for (int nt = 0; nt < 8; nt++)
#pragma unroll
        for (int j = 0; j < 4; j++) acc[nt][j] = 0.0f;

#pragma unroll 2
    for (int kt = 0; kt < 32; kt++) {
        size_t aoff = ((size_t)(mt * 32 + kt) * 32 + lane) * 16;
        uint4 ahi = ldcgu4(g_efh + aoff);
        uint4 alo = ldcgu4(g_efl + aoff);
#pragma unroll
        for (int p = 0; p < 4; p++) {
            uint4 bhv = smh[(kt * 4 + p) * 32 + lane];
            uint4 blv = sml[(kt * 4 + p) * 32 + lane];
            uint2 be = make_uint2(bhv.x, bhv.y), bo = make_uint2(bhv.z, bhv.w);
            uint2 le = make_uint2(blv.x, blv.y), lo = make_uint2(blv.z, blv.w);
            hmma(acc[2 * p], ahi, be);  hmma(acc[2 * p + 1], ahi, bo);
            hmma(acc[2 * p], alo, be);  hmma(acc[2 * p + 1], alo, bo);
            hmma(acc[2 * p], ahi, le);  hmma(acc[2 * p + 1], ahi, lo);
        }
    }

    const int gr = lane >> 2, gc = lane & 3;
    const int r0 = mt * 16 + gr, r1 = r0 + 8;
#pragma unroll
    for (int nt = 0; nt < 8; nt++) {
        int col = ct * 64 + nt * 8 + 2 * gc;
        const float* bias = (col < 1024) ? bz : bh;
        int cb = col & 1023;
        float b0 = bias[cb], b1 = bias[cb + 1];
        float2 v0 = make_float2(acc[nt][0] + b0, acc[nt][1] + b1);
        float2 v1 = make_float2(acc[nt][2] + b0, acc[nt][3] + b1);
        *(float2*)(g_pt + (size_t)r0 * 2048 + col) = v0;
        *(float2*)(g_pt + (size_t)r1 * 2048 + col) = v1;
    }
}

// ---------------------------------------------------------------------------
// Persistent HMMA recurrence v2: 64 CTAs x 256 thr (8 warps).
// warp w: kh = w>>2 (K half, 32 kt), mq = w&3 (m-tiles 2mq, 2mq+1).
// 3-product hi/lo: A_hi over 8 nt + A_lo over nt 0..3. One reduction round.
// ---------------------------------------------------------------------------
#define RED_OFF 131072
#define PTS_OFF 163840
#define RECUR_SMEM_BYTES 182272

__global__ __launch_bounds__(256, 1) void recur_kernel(const int* __restrict__ x) {
    extern __shared__ char smem[];
    uint4* bs4 = (uint4*)smem;
    float* red = (float*)(smem + RED_OFF);   // 4 mq * 2048 floats
    float* pts = (float*)(smem + PTS_OFF);   // 128 * 36 floats

    const int tid = threadIdx.x, lane = tid & 31, w = tid >> 5;
    const int nb = blockIdx.x;
    const int kh = w >> 2, mq = w & 3;
    const int mt0 = mq * 2, mt1 = mq * 2 + 1;
    const int gr = lane >> 2, gc = lane & 3;

    // load resident B fragments (128KB linear)
    {
        const uint4* src = (const uint4*)(g_bfrag + (size_t)nb * 131072);
        uint4* dst = (uint4*)smem;
#pragma unroll
        for (int i = 0; i < 32; i++) dst[tid + i * 256] = ldcgu4(src + tid + i * 256);
    }
    __syncthreads();

    float hold[2][8];
#pragma unroll
    for (int m = 0; m < 2; m++)
#pragma unroll
        for (int j = 0; j < 8; j++) hold[m][j] = 0.0f;

    for (int t = 0; t < SS; t++) {
        // ---- pt staging by kh=1 warps (one thread per batch row) ----
        if (kh == 1) {
            int r = mq * 32 + lane;
            int tok = __ldg(x + r * SS + t);
            const float* p = g_pt + (size_t)tok * 2048 + nb * 16;
#pragma unroll
            for (int i = 0; i < 4; i++)
                *(float4*)(pts + r * 36 + i * 4) = ldcg4(p + i * 4);
#pragma unroll
            for (int i = 0; i < 4; i++)
                *(float4*)(pts + r * 36 + 16 + i * 4) = ldcg4(p + 1024 + i * 4);
        }

        // ---- MMA phase: 768 HMMA per warp ----
        float acc[2][8][4];
#pragma unroll
        for (int m = 0; m < 2; m++)
#pragma unroll
            for (int nt = 0; nt < 8; nt++)
#pragma unroll
                for (int j = 0; j < 4; j++) acc[m][nt][j] = 0.0f;

#pragma unroll 2
        for (int i = 0; i < 32; i++) {
            int kt = kh * 32 + i;
            uint4 ah0 = ldcgu4(g_afrag + ((size_t)kt * 8 + mt0) * 512 + lane * 16);
            uint4 ah1 = ldcgu4(g_afrag + ((size_t)kt * 8 + mt1) * 512 + lane * 16);
            uint4 al0 = ldcgu4(g_afrag + ((size_t)(64 + kt) * 8 + mt0) * 512 + lane * 16);
            uint4 al1 = ldcgu4(g_afrag + ((size_t)(64 + kt) * 8 + mt1) * 512 + lane * 16);
            uint4 bq[4];
#pragma unroll
            for (int p = 0; p < 4; p++) bq[p] = bs4[(kt * 4 + p) * 32 + lane];
#pragma unroll
            for (int p = 0; p < 4; p++) {
                uint2 be = make_uint2(bq[p].x, bq[p].y);
                uint2 bo = make_uint2(bq[p].z, bq[p].w);
                hmma(acc[0][2 * p], ah0, be);  hmma(acc[0][2 * p + 1], ah0, bo);
                hmma(acc[1][2 * p], ah1, be);  hmma(acc[1][2 * p + 1], ah1, bo);
            }
#pragma unroll
            for (int p = 0; p < 2; p++) {    // lo pass: nt 0..3 (W_hi kinds)
                uint2 be = make_uint2(bq[p].x, bq[p].y);
                uint2 bo = make_uint2(bq[p].z, bq[p].w);
                hmma(acc[0][2 * p], al0, be);  hmma(acc[0][2 * p + 1], al0, bo);
                hmma(acc[1][2 * p], al1, be);  hmma(acc[1][2 * p + 1], al1, bo);
            }
        }

        // ---- single reduction round: kh1 -> kh0 ----
        __syncthreads();
        if (kh == 1) {
            float* dst = red + mq * 2048;
#pragma unroll
            for (int m = 0; m < 2; m++)
#pragma unroll
                for (int nt = 0; nt < 8; nt++)
                    *(float4*)(dst + (m * 8 + nt) * 128 + lane * 4) = *(float4*)acc[m][nt];
        }
        __syncthreads();

        // ---- gates + A-fragment writeback (kh0 warps) ----
        if (kh == 0) {
            const float* src = red + mq * 2048;
#pragma unroll
            for (int m = 0; m < 2; m++) {
#pragma unroll
                for (int nt = 0; nt < 8; nt++) {
                    float4 v = *(const float4*)(src + (m * 8 + nt) * 128 + lane * 4);
                    acc[m][nt][0] += v.x; acc[m][nt][1] += v.y;
                    acc[m][nt][2] += v.z; acc[m][nt][3] += v.w;
                }
                int mtg = mq * 2 + m;
                int r0 = mtg * 16 + gr, r1 = r0 + 8;
                const float* pr0 = pts + r0 * 36;
                const float* pr1 = pts + r1 * 36;
                float hn[8];
#pragma unroll
                for (int grp = 0; grp < 2; grp++) {
                    int n0 = grp, kc = 2 * gc + grp * 8;
                    float2 pz0 = *(const float2*)(pr0 + kc);
                    float2 ph0 = *(const float2*)(pr0 + 16 + kc);
                    float2 pz1 = *(const float2*)(pr1 + kc);
                    float2 ph1 = *(const float2*)(pr1 + 16 + kc);
                    float zp[4], hp[4];
#pragma unroll
                    for (int j = 0; j < 4; j++) {
                        zp[j] = acc[m][n0][j] + acc[m][n0 + 4][j];
                        hp[j] = acc[m][n0 + 2][j] + acc[m][n0 + 6][j];
                    }
                    float pzv[4] = {pz0.x, pz0.y, pz1.x, pz1.y};
                    float phv[4] = {ph0.x, ph0.y, ph1.x, ph1.y};
#pragma unroll
                    for (int j = 0; j < 4; j++) {
                        float z = 1.0f / (1.0f + __expf(-(zp[j] + pzv[j])));
                        float th = tanhf(hp[j] + phv[j]);
                        float ho = hold[m][grp * 4 + j];
                        float v = fmaf(z, th - ho, ho);
                        hn[grp * 4 + j] = v;
                        hold[m][grp * 4 + j] = v;
                    }
                }
                uint4 hi4, lo4;
                hi4.x = bfpair(hn[0], hn[1]);
                hi4.y = bfpair(hn[2], hn[3]);
                hi4.z = bfpair(hn[4], hn[5]);
                hi4.w = bfpair(hn[6], hn[7]);
                float r00 = hn[0] - __uint_as_float(hi4.x << 16);
                float r01 = hn[1] - __uint_as_float(hi4.x & 0xFFFF0000u);
                float r10 = hn[2] - __uint_as_float(hi4.y << 16);
                float r11 = hn[3] - __uint_as_float(hi4.y & 0xFFFF0000u);
                float r20 = hn[4] - __uint_as_float(hi4.z << 16);
                float r21 = hn[5] - __uint_as_float(hi4.z & 0xFFFF0000u);
                float r30 = hn[6] - __uint_as_float(hi4.w << 16);
                float r31 = hn[7] - __uint_as_float(hi4.w & 0xFFFF0000u);
                lo4.x = bfpair(r00, r01);
                lo4.y = bfpair(r10, r11);
                lo4.z = bfpair(r20, r21);
                lo4.w = bfpair(r30, r31);
                stcgu4(g_afrag + (size_t)((nb * 8) + mtg) * 512 + lane * 16, hi4);
                stcgu4(g_afrag + (size_t)(((64 + nb) * 8) + mtg) * 512 + lane * 16, lo4);
                if (t == SS - 1) {
                    int cb = nb * 16 + 2 * gc;
                    g_hf[r0 * HH + cb] = hn[0];
                    g_hf[r0 * HH + cb + 1] = hn[1];
                    g_hf[r1 * HH + cb] = hn[2];
                    g_hf[r1 * HH + cb + 1] = hn[3];
                    g_hf[r0 * HH + cb + 8] = hn[4];
                    g_hf[r0 * HH + cb + 9] = hn[5];
                    g_hf[r1 * HH + cb + 8] = hn[6];
                    g_hf[r1 * HH + cb + 9] = hn[7];
                }
            }
        }

        // ---- grid barrier ----
        __threadfence();
        __syncthreads();
        if (tid == 0) {
            atomicAdd(&g_bar, 1u);
            unsigned target = (unsigned)(t + 1) * 64u;
            const volatile unsigned* vb = (const volatile unsigned*)&g_bar;
            while (*vb < target) {}
        }
        __syncthreads();
    }
}

// ---------------------------------------------------------------------------
// Final classifier: out[128 x 1000] = h_final @ Wfc + bfc
// ---------------------------------------------------------------------------
#define FINAL_SMEM_FLOATS (8192 + 2 * 4224 + 1152)
__global__ __launch_bounds__(256) void final_kernel(const float* __restrict__ bfc,
                                                    float* __restrict__ out) {
    extern __shared__ float sm[];
    float* ws = sm;
    float* hsm = sm + 8192;
    float* red = sm + 8192 + 2 * 4224;
    const int tid = threadIdx.x;
    const int nb = blockIdx.x;
    const int c0 = nb * 8;
    const float* hin = g_hf;
    {
        const float4* src = (const float4*)(g_wfc3 + nb * 8192);
        float4* dst = (float4*)ws;
#pragma unroll
        for (int i = 0; i < 8; i++) dst[tid + i * 256] = src[tid + i * 256];
    }
    const int r = tid & 127, kh = tid >> 7;
    ull a0 = 0, a1 = 0, a2 = 0, a3 = 0;

    for (int j = 0; j < 16; j++) {
        __syncthreads();
#pragma unroll
        for (int i = 0; i < 8; i++) {
            int idx = tid + i * 256;
            int region = idx >> 10;
            int rem = idx & 1023;
            int rr = rem >> 3;
            int kq = (rem & 7) << 2;
            float4 hv = *(const float4*)(hin + rr * HH + region * 512 + j * 32 + kq);
            float* d = hsm + region * 4224 + rr * 33 + kq;
            d[0] = hv.x; d[1] = hv.y; d[2] = hv.z; d[3] = hv.w;
        }
        __syncthreads();
        const float* hrow = hsm + kh * 4224 + r * 33;
        const ulonglong2* wp = (const ulonglong2*)(ws + (kh * 512 + j * 32) * 8);
#pragma unroll
        for (int k = 0; k < 32; k++) {
            float hv = hrow[k];
            ull hh = pack2(hv, hv);
            ulonglong2 w0 = wp[k * 2];
            ulonglong2 w1 = wp[k * 2 + 1];
            ffma2(a0, hh, w0.x);
            ffma2(a1, hh, w0.y);
            ffma2(a2, hh, w1.x);
            ffma2(a3, hh, w1.y);
        }
    }
    float v[8];
    unpack2(a0, v[0], v[1]); unpack2(a1, v[2], v[3]);
    unpack2(a2, v[4], v[5]); unpack2(a3, v[6], v[7]);
    if (kh == 1) {
#pragma unroll
        for (int c = 0; c < 8; c++) red[r * 9 + c] = v[c];
    }
    __syncthreads();
    if (kh == 0) {
#pragma unroll
        for (int c = 0; c < 8; c++)
            out[r * NC + c0 + c] = v[c] + red[r * 9 + c] + bfc[c0 + c];
    }
}

// ---------------------------------------------------------------------------
extern "C" void kernel_launch(void* const* d_in, const int* in_sizes, int n_in,
                              void* d_out, int out_size) {
    const int*   x   = (const int*)  d_in[0];
    const float* emb = (const float*)d_in[1];
    const float* Wz  = (const float*)d_in[2];
    const float* bz  = (const float*)d_in[3];
    const float* Wh  = (const float*)d_in[4];
    const float* bh  = (const float*)d_in[5];
    const float* Wfc = (const float*)d_in[6];
    const float* bfc = (const float*)d_in[7];
    float* out = (float*)d_out;
    (void)in_sizes; (void)n_in; (void)out_size;

    const int final_smem = FINAL_SMEM_FLOATS * 4;
    cudaFuncSetAttribute(recur_kernel, cudaFuncAttributeMaxDynamicSharedMemorySize, RECUR_SMEM_BYTES);
    cudaFuncSetAttribute(ptable_hmma, cudaFuncAttributeMaxDynamicSharedMemorySize, 131072);
    cudaFuncSetAttribute(final_kernel, cudaFuncAttributeMaxDynamicSharedMemorySize, final_smem);

    prep_bfrag<<<8192, 256>>>(Wz, Wh);
    prep_efrag<<<32000, 256>>>(emb);
    prep_wtf<<<2048, 256>>>(Wz, Wh);
    prep_wfc<<<(125 * 1024 * 8 + 255) / 256, 256>>>(Wfc);
    zero_afrag<<<128, 256>>>();

    ptable_hmma<<<dim3(32, 250), 256, 131072>>>(bz, bh);

    recur_kernel<<<64, 256, RECUR_SMEM_BYTES>>>(x);

    final_kernel<<<125, 256, final_smem>>>(bfc, out);
}

// round 9
// speedup vs baseline: 5.5942x; 1.4396x over previous
#include <cuda_runtime.h>
#include <cuda_bf16.h>
#include <cstdint>

#define BB 128
#define SS 512
#define EE 512
#define HH 1024
#define VV 32000
#define NC 1000

typedef unsigned long long ull;

// ---------------- global scratch ----------------
__device__ float g_pt[(size_t)VV * 2048];          // token preacts (+bias)
__device__ unsigned char g_bfrag[128 * 65536];     // per-CTA recurrent B fragments (bf16)
__device__ unsigned char g_afrag[2 * 64 * 8 * 512];// h bf16 hi/lo A fragments: [pass][kt][mt][512B]
__device__ unsigned char g_efh[(size_t)2000 * 32 * 512];  // emb hi A-fragments
__device__ unsigned char g_efl[(size_t)2000 * 32 * 512];  // emb lo A-fragments
__device__ unsigned char g_wtfh[32 * 65536];       // Wtop hi B-fragments per col-tile
__device__ unsigned char g_wtfl[32 * 65536];       // Wtop lo B-fragments per col-tile
__device__ float g_wfc3[125 * 1024 * 8];           // classifier weights per block
__device__ float g_hf[BB * HH];                    // final hidden state fp32
__device__ unsigned g_bar;                         // grid barrier counter

// ---------------- helpers ----------------
__device__ __forceinline__ ull pack2(float a, float b) {
    ull r; asm("mov.b64 %0, {%1, %2};" : "=l"(r) : "f"(a), "f"(b)); return r;
}
__device__ __forceinline__ void unpack2(ull v, float& a, float& b) {
    asm("mov.b64 {%0, %1}, %2;" : "=f"(a), "=f"(b) : "l"(v));
}
__device__ __forceinline__ void ffma2(ull& d, ull a, ull b) {
    asm("fma.rn.f32x2 %0, %1, %2, %0;" : "+l"(d) : "l"(a), "l"(b));
}
__device__ __forceinline__ float4 ldcg4(const void* p) {
    float4 v;
    asm volatile("ld.global.cg.v4.f32 {%0,%1,%2,%3},[%4];"
                 : "=f"(v.x), "=f"(v.y), "=f"(v.z), "=f"(v.w) : "l"(p));
    return v;
}
__device__ __forceinline__ uint4 ldcgu4(const void* p) {
    uint4 v;
    asm volatile("ld.global.cg.v4.b32 {%0,%1,%2,%3},[%4];"
                 : "=r"(v.x), "=r"(v.y), "=r"(v.z), "=r"(v.w) : "l"(p));
    return v;
}
__device__ __forceinline__ void stcgu2(void* p, uint2 v) {
    asm volatile("st.global.cg.v2.b32 [%0],{%1,%2};"
                 :: "l"(p), "r"(v.x), "r"(v.y) : "memory");
}
__device__ __forceinline__ uint32_t bfpair(float v0, float v1) {
    uint32_t r; asm("cvt.rn.bf16x2.f32 %0, %1, %2;" : "=r"(r) : "f"(v1), "f"(v0)); return r;
}
__device__ __forceinline__ void hmma(float* d, const uint4& a, const uint2& b) {
    asm("mma.sync.aligned.m16n8k16.row.col.f32.bf16.bf16.f32 "
        "{%0,%1,%2,%3},{%4,%5,%6,%7},{%8,%9},{%0,%1,%2,%3};"
        : "+f"(d[0]), "+f"(d[1]), "+f"(d[2]), "+f"(d[3])
        : "r"(a.x), "r"(a.y), "r"(a.z), "r"(a.w), "r"(b.x), "r"(b.y));
}

// ---------------------------------------------------------------------------
// Prep: recurrent W -> B fragments for 128 CTAs x 32 cols.
// nt: 0=Wz_hi 1=Wh_hi 2=Wz_lo 3=Wh_lo, local col = l>>2 (8 cols per CTA).
// idx = nb*16384 + ((kt*2 + (nt>>1))*32 + l)*4 + (nt&1)*2 + b
// ---------------------------------------------------------------------------
__global__ void prep_bfrag(const float* __restrict__ Wz, const float* __restrict__ Wh) {
    int o = blockIdx.x * blockDim.x + threadIdx.x;   // 2097152
    int b = o & 1, l = (o >> 1) & 31, nt = (o >> 6) & 3, kt = (o >> 8) & 63, nb = o >> 14;
    int k = kt * 16 + (l & 3) * 2 + b * 8;
    int hcol = nb * 8 + (l >> 2);
    const float* W = (nt & 1) ? Wh : Wz;
    float w0 = W[(size_t)(512 + k) * 1024 + hcol];
    float w1 = W[(size_t)(512 + k + 1) * 1024 + hcol];
    uint32_t hi = bfpair(w0, w1);
    uint32_t val;
    if (nt < 2) val = hi;
    else {
        float r0 = w0 - __uint_as_float(hi << 16);
        float r1 = w1 - __uint_as_float(hi & 0xFFFF0000u);
        val = bfpair(r0, r1);
    }
    ((uint32_t*)g_bfrag)[(size_t)nb * 16384 + (size_t)((kt * 2 + (nt >> 1)) * 32 + l) * 4 + (nt & 1) * 2 + b] = val;
}

// emb -> hi/lo A fragments: [mt 2000][kt 32][512B]
__global__ void prep_efrag(const float* __restrict__ emb) {
    int o = blockIdx.x * blockDim.x + threadIdx.x;   // 8192000
    int j = o & 3, l = (o >> 2) & 31, kt = (o >> 7) & 31, mt = o >> 12;
    int r = mt * 16 + (j & 1) * 8 + (l >> 2);
    int k = kt * 16 + (j >> 1) * 8 + (l & 3) * 2;
    float e0 = emb[(size_t)r * EE + k];
    float e1 = emb[(size_t)r * EE + k + 1];
    uint32_t hi = bfpair(e0, e1);
    float r0 = e0 - __uint_as_float(hi << 16);
    float r1 = e1 - __uint_as_float(hi & 0xFFFF0000u);
    size_t idx = ((size_t)(mt * 32 + kt) * 32 + l) * 4 + j;
    ((uint32_t*)g_efh)[idx] = hi;
    ((uint32_t*)g_efl)[idx] = bfpair(r0, r1);
}

// Wtop -> hi/lo B fragments per col-tile
__global__ void prep_wtf(const float* __restrict__ Wz, const float* __restrict__ Wh) {
    int o = blockIdx.x * blockDim.x + threadIdx.x;   // 524288
    int j = o & 3, l = (o >> 2) & 31, ntp = (o >> 7) & 3, kt = (o >> 9) & 31, ct = o >> 14;
    int nt = ntp * 2 + (j >> 1);
    int breg = j & 1;
    int colg = ct * 64 + nt * 8 + (l >> 2);
    int k = kt * 16 + (l & 3) * 2 + breg * 8;
    const float* W = (colg < 1024) ? Wz : Wh;
    int c = colg & 1023;
    float w0 = W[(size_t)k * 1024 + c];
    float w1 = W[(size_t)(k + 1) * 1024 + c];
    uint32_t hi = bfpair(w0, w1);
    float r0 = w0 - __uint_as_float(hi << 16);
    float r1 = w1 - __uint_as_float(hi & 0xFFFF0000u);
    ((uint32_t*)g_wtfh)[o] = hi;
    ((uint32_t*)g_wtfl)[o] = bfpair(r0, r1);
}

__global__ void prep_wfc(const float* __restrict__ Wfc) {
    int o = blockIdx.x * blockDim.x + threadIdx.x;
    if (o >= 125 * 1024 * 8) return;
    int c = o & 7, k = (o >> 3) & 1023, nb = o >> 13;
    g_wfc3[o] = Wfc[(size_t)k * NC + nb * 8 + c];
}

__global__ void zero_afrag() {
    int i = blockIdx.x * blockDim.x + threadIdx.x;   // 32768 uint4
    ((uint4*)g_afrag)[i] = make_uint4(0, 0, 0, 0);
    if (i == 0) g_bar = 0u;
}

// ---------------------------------------------------------------------------
// ptable via HMMA (unchanged from R8)
// ---------------------------------------------------------------------------
__global__ __launch_bounds__(256) void ptable_hmma(const float* __restrict__ bz,
                                                   const float* __restrict__ bh) {
    extern __shared__ char smem[];
    uint4* smh = (uint4*)smem;
    uint4* sml = (uint4*)(smem + 65536);
    const int tid = threadIdx.x, lane = tid & 31, w = tid >> 5;
    const int ct = blockIdx.x, rt = blockIdx.y;
    const int mt = rt * 8 + w;

    {
        const uint4* sh = (const uint4*)(g_wtfh + (size_t)ct * 65536);
        const uint4* sl = (const uint4*)(g_wtfl + (size_t)ct * 65536);
#pragma unroll
        for (int i = 0; i < 16; i++) {
            smh[tid + i * 256] = ldcgu4(sh + tid + i * 256);
            sml[tid + i * 256] = ldcgu4(sl + tid + i * 256);
        }
    }
    __syncthreads();

    float acc[8][4];
#pragma unroll
    for (int nt = 0; nt < 8; nt++)
#pragma unroll
        for (int j = 0; j < 4; j++) acc[nt][j] = 0.0f;

#pragma unroll 2
    for (int kt = 0; kt < 32; kt++) {
        size_t aoff = ((size_t)(mt * 32 + kt) * 32 + lane) * 16;
        uint4 ahi = ldcgu4(g_efh + aoff);
        uint4 alo = ldcgu4(g_efl + aoff);
#pragma unroll
        for (int p = 0; p < 4; p++) {
            uint4 bhv = smh[(kt * 4 + p) * 32 + lane];
            uint4 blv = sml[(kt * 4 + p) * 32 + lane];
            uint2 be = make_uint2(bhv.x, bhv.y), bo = make_uint2(bhv.z, bhv.w);
            uint2 le = make_uint2(blv.x, blv.y), lo = make_uint2(blv.z, blv.w);
            hmma(acc[2 * p], ahi, be);  hmma(acc[2 * p + 1], ahi, bo);
            hmma(acc[2 * p], alo, be);  hmma(acc[2 * p + 1], alo, bo);
            hmma(acc[2 * p], ahi, le);  hmma(acc[2 * p + 1], ahi, lo);
        }
    }

    const int gr = lane >> 2, gc = lane & 3;
    const int r0 = mt * 16 + gr, r1 = r0 + 8;
#pragma unroll
    for (int nt = 0; nt < 8; nt++) {
        int col = ct * 64 + nt * 8 + 2 * gc;
        const float* bias = (col < 1024) ? bz : bh;
        int cb = col & 1023;
        float b0 = bias[cb], b1 = bias[cb + 1];
        float2 v0 = make_float2(acc[nt][0] + b0, acc[nt][1] + b1);
        float2 v1 = make_float2(acc[nt][2] + b0, acc[nt][3] + b1);
        *(float2*)(g_pt + (size_t)r0 * 2048 + col) = v0;
        *(float2*)(g_pt + (size_t)r1 * 2048 + col) = v1;
    }
}

// ---------------------------------------------------------------------------
// Persistent HMMA recurrence v3: 128 CTAs x 256 thr (8 warps).
// CTA nb owns 8 h-cols. warp w: kh = w>>2, mq = w&3 (m-tiles 2mq, 2mq+1).
// B = 32 cols [Wz_hi|Wh_hi|Wz_lo|Wh_lo]x8. Per warp 384 HMMA, pipelined loads.
// Fold: z = acc[nt0]+acc[nt2], ht = acc[nt1]+acc[nt3] (thread-local).
// ---------------------------------------------------------------------------
#define RED_OFF 65536
#define PTS_OFF (65536 + 16384)
#define RECUR_SMEM_BYTES (65536 + 16384 + 128 * 20 * 4)

__global__ __launch_bounds__(256, 1) void recur_kernel(const int* __restrict__ x) {
    extern __shared__ char smem[];
    uint4* bs4 = (uint4*)smem;               // 64KB B fragments
    float* red = (float*)(smem + RED_OFF);   // 16KB: 4 mq x 1024 floats
    float* pts = (float*)(smem + PTS_OFF);   // 128 x 20 floats

    const int tid = threadIdx.x, lane = tid & 31, w = tid >> 5;
    const int nb = blockIdx.x;
    const int kh = w >> 2, mq = w & 3;
    const int mt0 = mq * 2, mt1 = mq * 2 + 1;
    const int gr = lane >> 2, gc = lane & 3;
    const int ktw = nb >> 1;                 // writeback kt
    const int half = (nb & 1) * 8;           // byte offset within fragment

    // load resident B fragments (64KB linear)
    {
        const uint4* src = (const uint4*)(g_bfrag + (size_t)nb * 65536);
#pragma unroll
        for (int i = 0; i < 16; i++) bs4[tid + i * 256] = ldcgu4(src + tid + i * 256);
    }
    __syncthreads();

    float hold[2][4];
#pragma unroll
    for (int m = 0; m < 2; m++)
#pragma unroll
        for (int j = 0; j < 4; j++) hold[m][j] = 0.0f;

    for (int t = 0; t < SS; t++) {
        // ---- pt staging by kh=1 warps ----
        if (kh == 1) {
            int r = mq * 32 + lane;
            int tok = __ldg(x + r * SS + t);
            const float* p = g_pt + (size_t)tok * 2048 + nb * 8;
            *(float4*)(pts + r * 20) = ldcg4(p);
            *(float4*)(pts + r * 20 + 4) = ldcg4(p + 4);
            *(float4*)(pts + r * 20 + 8) = ldcg4(p + 1024);
            *(float4*)(pts + r * 20 + 12) = ldcg4(p + 1028);
        }

        // ---- MMA phase: 384 HMMA per warp, ping-pong pipelined ----
        float acc[2][4][4];
#pragma unroll
        for (int m = 0; m < 2; m++)
#pragma unroll
            for (int nt = 0; nt < 4; nt++)
#pragma unroll
                for (int j = 0; j < 4; j++) acc[m][nt][j] = 0.0f;

        uint4 ah[2][2], al[2][2], bq[2][2];
        {
            int kt = kh * 32;
            ah[0][0] = ldcgu4(g_afrag + ((size_t)kt * 8 + mt0) * 512 + lane * 16);
            ah[0][1] = ldcgu4(g_afrag + ((size_t)kt * 8 + mt1) * 512 + lane * 16);
            al[0][0] = ldcgu4(g_afrag + ((size_t)(64 + kt) * 8 + mt0) * 512 + lane * 16);
            al[0][1] = ldcgu4(g_afrag + ((size_t)(64 + kt) * 8 + mt1) * 512 + lane * 16);
            bq[0][0] = bs4[(kt * 2) * 32 + lane];
            bq[0][1] = bs4[(kt * 2 + 1) * 32 + lane];
        }
#pragma unroll
        for (int i = 0; i < 32; i++) {
            const int cur = i & 1, nxt = cur ^ 1;
            if (i < 31) {
                int kt = kh * 32 + i + 1;
                ah[nxt][0] = ldcgu4(g_afrag + ((size_t)kt * 8 + mt0) * 512 + lane * 16);
                ah[nxt][1] = ldcgu4(g_afrag + ((size_t)kt * 8 + mt1) * 512 + lane * 16);
                al[nxt][0] = ldcgu4(g_afrag + ((size_t)(64 + kt) * 8 + mt0) * 512 + lane * 16);
                al[nxt][1] = ldcgu4(g_afrag + ((size_t)(64 + kt) * 8 + mt1) * 512 + lane * 16);
                bq[nxt][0] = bs4[(kt * 2) * 32 + lane];
                bq[nxt][1] = bs4[(kt * 2 + 1) * 32 + lane];
            }
            uint2 b0 = make_uint2(bq[cur][0].x, bq[cur][0].y);
            uint2 b1 = make_uint2(bq[cur][0].z, bq[cur][0].w);
            uint2 b2 = make_uint2(bq[cur][1].x, bq[cur][1].y);
            uint2 b3 = make_uint2(bq[cur][1].z, bq[cur][1].w);
#pragma unroll
            for (int m = 0; m < 2; m++) {
                hmma(acc[m][0], ah[cur][m], b0);
                hmma(acc[m][1], ah[cur][m], b1);
                hmma(acc[m][2], ah[cur][m], b2);
                hmma(acc[m][3], ah[cur][m], b3);
                hmma(acc[m][0], al[cur][m], b0);
                hmma(acc[m][1], al[cur][m], b1);
            }
        }

        // ---- single reduction round: kh1 -> kh0 ----
        __syncthreads();
        if (kh == 1) {
            float* dst = red + mq * 1024;
#pragma unroll
            for (int m = 0; m < 2; m++)
#pragma unroll
                for (int nt = 0; nt < 4; nt++)
                    *(float4*)(dst + (m * 4 + nt) * 128 + lane * 4) = *(float4*)acc[m][nt];
        }
        __syncthreads();

        // ---- gates + A-fragment writeback (kh0 warps) ----
        if (kh == 0) {
            const float* src = red + mq * 1024;
#pragma unroll
            for (int m = 0; m < 2; m++) {
#pragma unroll
                for (int nt = 0; nt < 4; nt++) {
                    float4 v = *(const float4*)(src + (m * 4 + nt) * 128 + lane * 4);
                    acc[m][nt][0] += v.x; acc[m][nt][1] += v.y;
                    acc[m][nt][2] += v.z; acc[m][nt][3] += v.w;
                }
                int mtg = mq * 2 + m;
                int r0 = mtg * 16 + gr, r1 = r0 + 8;
                float hn[4];
                {
                    float zp[4], hp[4];
#pragma unroll
                    for (int j = 0; j < 4; j++) {
                        zp[j] = acc[m][0][j] + acc[m][2][j];
                        hp[j] = acc[m][1][j] + acc[m][3][j];
                    }
                    float2 pz0 = *(const float2*)(pts + r0 * 20 + 2 * gc);
                    float2 ph0 = *(const float2*)(pts + r0 * 20 + 8 + 2 * gc);
                    float2 pz1 = *(const float2*)(pts + r1 * 20 + 2 * gc);
                    float2 ph1 = *(const float2*)(pts + r1 * 20 + 8 + 2 * gc);
                    float pzv[4] = {pz0.x, pz0.y, pz1.x, pz1.y};
                    float phv[4] = {ph0.x, ph0.y, ph1.x, ph1.y};
#pragma unroll
                    for (int j = 0; j < 4; j++) {
                        float z = 1.0f / (1.0f + __expf(-(zp[j] + pzv[j])));
                        float th = tanhf(hp[j] + phv[j]);
                        float ho = hold[m][j];
                        float v = fmaf(z, th - ho, ho);
                        hn[j] = v;
                        hold[m][j] = v;
                    }
                }
                // half-fragment writeback: (a.x,a.y) or (a.z,a.w)
                uint32_t h0 = bfpair(hn[0], hn[1]);   // row r0, cols 2gc,2gc+1
                uint32_t h1 = bfpair(hn[2], hn[3]);   // row r1
                float l00 = hn[0] - __uint_as_float(h0 << 16);
                float l01 = hn[1] - __uint_as_float(h0 & 0xFFFF0000u);
                float l10 = hn[2] - __uint_as_float(h1 << 16);
                float l11 = hn[3] - __uint_as_float(h1 & 0xFFFF0000u);
                uint2 hiv = make_uint2(h0, h1);
                uint2 lov = make_uint2(bfpair(l00, l01), bfpair(l10, l11));
                stcgu2(g_afrag + ((size_t)ktw * 8 + mtg) * 512 + lane * 16 + half, hiv);
                stcgu2(g_afrag + ((size_t)(64 + ktw) * 8 + mtg) * 512 + lane * 16 + half, lov);
                if (t == SS - 1) {
                    int cb = nb * 8 + 2 * gc;
                    g_hf[r0 * HH + cb] = hn[0];
                    g_hf[r0 * HH + cb + 1] = hn[1];
                    g_hf[r1 * HH + cb] = hn[2];
                    g_hf[r1 * HH + cb + 1] = hn[3];
                }
            }
        }

        // ---- grid barrier ----
        __threadfence();
        __syncthreads();
        if (tid == 0) {
            atomicAdd(&g_bar, 1u);
            unsigned target = (unsigned)(t + 1) * 128u;
            const volatile unsigned* vb = (const volatile unsigned*)&g_bar;
            while (*vb < target) {}
        }
        __syncthreads();
    }
}

// ---------------------------------------------------------------------------
// Final classifier: out[128 x 1000] = h_final @ Wfc + bfc
// ---------------------------------------------------------------------------
#define FINAL_SMEM_FLOATS (8192 + 2 * 4224 + 1152)
__global__ __launch_bounds__(256) void final_kernel(const float* __restrict__ bfc,
                                                    float* __restrict__ out) {
    extern __shared__ float sm[];
    float* ws = sm;
    float* hsm = sm + 8192;
    float* red = sm + 8192 + 2 * 4224;
    const int tid = threadIdx.x;
    const int nb = blockIdx.x;
    const int c0 = nb * 8;
    const float* hin = g_hf;
    {
        const float4* src = (const float4*)(g_wfc3 + nb * 8192);
        float4* dst = (float4*)ws;
#pragma unroll
        for (int i = 0; i < 8; i++) dst[tid + i * 256] = src[tid + i * 256];
    }
    const int r = tid & 127, kh = tid >> 7;
    ull a0 = 0, a1 = 0, a2 = 0, a3 = 0;

    for (int j = 0; j < 16; j++) {
        __syncthreads();
#pragma unroll
        for (int i = 0; i < 8; i++) {
            int idx = tid + i * 256;
            int region = idx >> 10;
            int rem = idx & 1023;
            int rr = rem >> 3;
            int kq = (rem & 7) << 2;
            float4 hv = *(const float4*)(hin + rr * HH + region * 512 + j * 32 + kq);
            float* d = hsm + region * 4224 + rr * 33 + kq;
            d[0] = hv.x; d[1] = hv.y; d[2] = hv.z; d[3] = hv.w;
        }
        __syncthreads();
        const float* hrow = hsm + kh * 4224 + r * 33;
        const ulonglong2* wp = (const ulonglong2*)(ws + (kh * 512 + j * 32) * 8);
#pragma unroll
        for (int k = 0; k < 32; k++) {
            float hv = hrow[k];
            ull hh = pack2(hv, hv);
            ulonglong2 w0 = wp[k * 2];
            ulonglong2 w1 = wp[k * 2 + 1];
            ffma2(a0, hh, w0.x);
            ffma2(a1, hh, w0.y);
            ffma2(a2, hh, w1.x);
            ffma2(a3, hh, w1.y);
        }
    }
    float v[8];
    unpack2(a0, v[0], v[1]); unpack2(a1, v[2], v[3]);
    unpack2(a2, v[4], v[5]); unpack2(a3, v[6], v[7]);
    if (kh == 1) {
#pragma unroll
        for (int c = 0; c < 8; c++) red[r * 9 + c] = v[c];
    }
    __syncthreads();
    if (kh == 0) {
#pragma unroll
        for (int c = 0; c < 8; c++)
            out[r * NC + c0 + c] = v[c] + red[r * 9 + c] + bfc[c0 + c];
    }
}

// ---------------------------------------------------------------------------
extern "C" void kernel_launch(void* const* d_in, const int* in_sizes, int n_in,
                              void* d_out, int out_size) {
    const int*   x   = (const int*)  d_in[0];
    const float* emb = (const float*)d_in[1];
    const float* Wz  = (const float*)d_in[2];
    const float* bz  = (const float*)d_in[3];
    const float* Wh  = (const float*)d_in[4];
    const float* bh  = (const float*)d_in[5];
    const float* Wfc = (const float*)d_in[6];
    const float* bfc = (const float*)d_in[7];
    float* out = (float*)d_out;
    (void)in_sizes; (void)n_in; (void)out_size;

    const int final_smem = FINAL_SMEM_FLOATS * 4;
    cudaFuncSetAttribute(recur_kernel, cudaFuncAttributeMaxDynamicSharedMemorySize, RECUR_SMEM_BYTES);
    cudaFuncSetAttribute(ptable_hmma, cudaFuncAttributeMaxDynamicSharedMemorySize, 131072);
    cudaFuncSetAttribute(final_kernel, cudaFuncAttributeMaxDynamicSharedMemorySize, final_smem);

    prep_bfrag<<<8192, 256>>>(Wz, Wh);
    prep_efrag<<<32000, 256>>>(emb);
    prep_wtf<<<2048, 256>>>(Wz, Wh);
    prep_wfc<<<(125 * 1024 * 8 + 255) / 256, 256>>>(Wfc);
    zero_afrag<<<128, 256>>>();

    ptable_hmma<<<dim3(32, 250), 256, 131072>>>(bz, bh);

    recur_kernel<<<128, 256, RECUR_SMEM_BYTES>>>(x);

    final_kernel<<<125, 256, final_smem>>>(bfc, out);
}